// round 13
// baseline (speedup 1.0000x reference)
#include <cuda_runtime.h>
#include <cuda_bf16.h>
#include <cuda_fp16.h>
#include <cstdint>

#define N_ATOMS 50000
#define N_PAIRS 800000
#define N_EMB   128
#define N_DIST  100
#define N_HID   128
#define BSTR    136          // padded element row stride (272 B for 2B types)
#define TROWS_A 256          // atoms rows per CTA
#define TROWS_P 128          // pairs rows per CTA (2 CTAs/SM)
#define ATOM_CTAS ((N_ATOMS + TROWS_A - 1) / TROWS_A)   // 196

typedef unsigned long long ull;
typedef unsigned short ushort_t;

// ---------------- device scratch ----------------
__device__ __align__(16) unsigned g_afh2[(size_t)N_ATOMS * N_HID];
__device__ __align__(16) __half g_Bdf_h[128 * BSTR];
__device__ __align__(16) __half g_Bdf_l[128 * BSTR];
__device__ __align__(16) __half g_Bfc_h[128 * BSTR];
__device__ __align__(16) __half g_Bfc_l[128 * BSTR];

// ---------------- helpers ----------------
static __device__ __forceinline__ float fast_tanh(float x) {
    float e = __expf(2.0f * x);
    return 1.0f - __fdividef(2.0f, e + 1.0f);
}
static __device__ __forceinline__ void split_bf(float x, ushort_t &h, ushort_t &l) {
    __nv_bfloat16 bh = __float2bfloat16(x);
    float r = x - __bfloat162float(bh);
    __nv_bfloat16 bl = __float2bfloat16(r);
    h = __bfloat16_as_ushort(bh);
    l = __bfloat16_as_ushort(bl);
}
static __device__ __forceinline__ void split_fp16(float x, ushort_t &h, ushort_t &l) {
    __half hh = __float2half_rn(x);
    float r = x - __half2float(hh);
    __half hl = __float2half_rn(r);
    h = __half_as_ushort(hh);
    l = __half_as_ushort(hl);
}
static __device__ __forceinline__ float unsplit(unsigned p) {
    return __bfloat162float(__ushort_as_bfloat16((ushort_t)(p & 0xFFFF)))
         + __bfloat162float(__ushort_as_bfloat16((ushort_t)(p >> 16)));
}
static __device__ __forceinline__ uint32_t smem_u32(const void* p) {
    uint32_t a;
    asm("{ .reg .u64 t; cvta.to.shared.u64 t, %1; cvt.u32.u64 %0, t; }"
        : "=r"(a) : "l"(p));
    return a;
}
static __device__ __forceinline__ void ldsm4(uint32_t* r, uint32_t addr) {
    asm volatile("ldmatrix.sync.aligned.m8n8.x4.shared.b16 {%0,%1,%2,%3}, [%4];"
                 : "=r"(r[0]), "=r"(r[1]), "=r"(r[2]), "=r"(r[3]) : "r"(addr));
}
static __device__ __forceinline__ void mma_bf16(float* d, const uint32_t* a,
                                                const uint32_t* b) {
    asm volatile(
        "mma.sync.aligned.m16n8k16.row.col.f32.bf16.bf16.f32 "
        "{%0,%1,%2,%3}, {%4,%5,%6,%7}, {%8,%9}, {%0,%1,%2,%3};"
        : "+f"(d[0]), "+f"(d[1]), "+f"(d[2]), "+f"(d[3])
        : "r"(a[0]), "r"(a[1]), "r"(a[2]), "r"(a[3]), "r"(b[0]), "r"(b[1]));
}
static __device__ __forceinline__ void mma_f16(float* d, const uint32_t* a,
                                               const uint32_t* b) {
    asm volatile(
        "mma.sync.aligned.m16n8k16.row.col.f32.f16.f16.f32 "
        "{%0,%1,%2,%3}, {%4,%5,%6,%7}, {%8,%9}, {%0,%1,%2,%3};"
        : "+f"(d[0]), "+f"(d[1]), "+f"(d[2]), "+f"(d[3])
        : "r"(a[0]), "r"(a[1]), "r"(a[2]), "r"(a[3]), "r"(b[0]), "r"(b[1]));
}

// ---------------- atoms kernel SMEM layout (bf16 3-term) -----------------
#define ASM_IS    0
#define ASM_JS    1024
#define ASM_AHI   2560
#define ASM_ALO   (ASM_AHI + 69632)
#define ASM_BHI   (ASM_ALO + 69632)
#define ASM_BLO   (ASM_BHI + 34816)
#define ASM_TOTAL (ASM_BLO + 34816)        // 211456 B

// ---------------- pairs kernel SMEM layout (fp16 2-term, 128 rows) -------
#define PSM_IS    0                        // 128 int (512 B)
#define PSM_JS    512                      // 128 int (512 B)
#define PSM_BDF   1024                     // 128 float (512 B)
#define PSM_A     1536                     // 128 x 136 fp16 = 34816 B
#define PSM_BH    (PSM_A + 34816)          // 36352 (34816 B)
#define PSM_BL    (PSM_BH + 34816)         // 71168 (34816 B)
#define PSM_TOTAL (PSM_BL + 34816)         // 105984 B -> 2 CTAs/SM
#define PSM_MSG   PSM_A                    // fp32 msg 128x129 = 66048 B,
                                           // overlays A + BH (dead post-GEMM2)

// =====================================================================
// Warp GEMM, bf16 3-term (atoms): D[256,128], 16 warps, warp tile 64x32.
// =====================================================================
template<int KSTEPS>
static __device__ __forceinline__ void do_gemm3(
    uint32_t aHi, uint32_t aLo, uint32_t bHi, uint32_t bLo,
    uint32_t aoff0, uint32_t boff0, float* d)
{
#pragma unroll 1
    for (int ks = 0; ks < KSTEPS; ks++) {
        uint32_t Ah[4][4], Al[4][4], Bh[4][2], Bl[4][2];
#pragma unroll
        for (int mt = 0; mt < 4; mt++) {
            uint32_t off = aoff0 + mt * (16 * BSTR * 2) + ks * 32;
            ldsm4(Ah[mt], aHi + off);
            ldsm4(Al[mt], aLo + off);
        }
#pragma unroll
        for (int np = 0; np < 2; np++) {
            uint32_t off = boff0 + np * (16 * BSTR * 2) + ks * 32;
            uint32_t th[4], tl[4];
            ldsm4(th, bHi + off);
            ldsm4(tl, bLo + off);
            Bh[2*np][0] = th[0]; Bh[2*np][1] = th[1];
            Bh[2*np+1][0] = th[2]; Bh[2*np+1][1] = th[3];
            Bl[2*np][0] = tl[0]; Bl[2*np][1] = tl[1];
            Bl[2*np+1][0] = tl[2]; Bl[2*np+1][1] = tl[3];
        }
#pragma unroll
        for (int mt = 0; mt < 4; mt++)
#pragma unroll
            for (int nt = 0; nt < 4; nt++) {
                float* dd = d + (mt * 4 + nt) * 4;
                mma_bf16(dd, Ah[mt], Bh[nt]);
                mma_bf16(dd, Ah[mt], Bl[nt]);
                mma_bf16(dd, Al[mt], Bh[nt]);
            }
    }
}

// =====================================================================
// Warp GEMM, fp16 2-term (pairs): A single image, B hi/lo.
// =====================================================================
template<int KSTEPS>
static __device__ __forceinline__ void do_gemm2(
    uint32_t aBase, uint32_t bHi, uint32_t bLo,
    uint32_t aoff0, uint32_t boff0, float* d)
{
#pragma unroll 1
    for (int ks = 0; ks < KSTEPS; ks++) {
        uint32_t Ah[4][4], Bh[4][2], Bl[4][2];
#pragma unroll
        for (int mt = 0; mt < 4; mt++) {
            uint32_t off = aoff0 + mt * (16 * BSTR * 2) + ks * 32;
            ldsm4(Ah[mt], aBase + off);
        }
#pragma unroll
        for (int np = 0; np < 2; np++) {
            uint32_t off = boff0 + np * (16 * BSTR * 2) + ks * 32;
            uint32_t th[4], tl[4];
            ldsm4(th, bHi + off);
            ldsm4(tl, bLo + off);
            Bh[2*np][0] = th[0]; Bh[2*np][1] = th[1];
            Bh[2*np+1][0] = th[2]; Bh[2*np+1][1] = th[3];
            Bl[2*np][0] = tl[0]; Bl[2*np][1] = tl[1];
            Bl[2*np+1][0] = tl[2]; Bl[2*np+1][1] = tl[3];
        }
#pragma unroll
        for (int mt = 0; mt < 4; mt++)
#pragma unroll
            for (int nt = 0; nt < 4; nt++) {
                float* dd = d + (mt * 4 + nt) * 4;
                mma_f16(dd, Ah[mt], Bh[nt]);
                mma_f16(dd, Ah[mt], Bl[nt]);
            }
    }
}

// ======== staging helpers ========
static __device__ __forceinline__ void stage_splits_bf(
    char* smc, const float* __restrict__ src, int base, int nrows, int tid)
{
    const int srow  = tid >> 1;
    const int shalf = tid & 1;
    const int q0 = shalf ? 16 : 0;
    const int q1 = shalf ? 32 : 16;
    char* ah = smc + ASM_AHI + srow * (BSTR * 2);
    char* al = smc + ASM_ALO + srow * (BSTR * 2);
    if (srow < nrows) {
        const float4* dr = (const float4*)(src + (size_t)(base + srow) * 128);
#pragma unroll
        for (int q = q0; q < q1; q++) {
            float4 v = dr[q];
            ushort_t h0,l0,h1,l1,h2,l2,h3,l3;
            split_bf(v.x, h0, l0); split_bf(v.y, h1, l1);
            split_bf(v.z, h2, l2); split_bf(v.w, h3, l3);
            *(unsigned*)(ah + 8 * q)     = (unsigned)h0 | ((unsigned)h1 << 16);
            *(unsigned*)(ah + 8 * q + 4) = (unsigned)h2 | ((unsigned)h3 << 16);
            *(unsigned*)(al + 8 * q)     = (unsigned)l0 | ((unsigned)l1 << 16);
            *(unsigned*)(al + 8 * q + 4) = (unsigned)l2 | ((unsigned)l3 << 16);
        }
    } else {
        for (int q = q0; q < q1; q++) {
            *(ull*)(ah + 8 * q) = 0ULL;
            *(ull*)(al + 8 * q) = 0ULL;
        }
    }
}
// fp16 single-image staging of distance (2 threads per row)
static __device__ __forceinline__ void stage_half(
    char* smc, const float* __restrict__ src, int base, int tid)
{
    const int srow  = tid >> 1;              // 0..127
    const int shalf = tid & 1;
    const int q0 = shalf ? 13 : 0;
    const int q1 = shalf ? 25 : 13;
    char* ap = smc + PSM_A + srow * (BSTR * 2);
    const float4* dr = (const float4*)(src + (size_t)(base + srow) * N_DIST);
#pragma unroll
    for (int q = q0; q < q1; q++) {
        float4 v = dr[q];
        unsigned u01 = (unsigned)__half_as_ushort(__float2half_rn(v.x))
                     | ((unsigned)__half_as_ushort(__float2half_rn(v.y)) << 16);
        unsigned u23 = (unsigned)__half_as_ushort(__float2half_rn(v.z))
                     | ((unsigned)__half_as_ushort(__float2half_rn(v.w)) << 16);
        *(unsigned*)(ap + 8 * q)     = u01;
        *(unsigned*)(ap + 8 * q + 4) = u23;
    }
    if (shalf) {
#pragma unroll
        for (int c = 100; c < 112; c += 2)   // zero pad for kstep 6
            *(unsigned*)(ap + c * 2) = 0u;
    }
}
static __device__ __forceinline__ void stage_w_direct(
    char* smc, const float* __restrict__ W, int tid)
{
    __nv_bfloat16* bh = (__nv_bfloat16*)(smc + ASM_BHI);
    __nv_bfloat16* bl = (__nv_bfloat16*)(smc + ASM_BLO);
    for (int idx = tid; idx < 16384; idx += 512) {
        int k = idx >> 7, n = idx & 127;
        ushort_t h, l;
        split_bf(W[idx], h, l);
        bh[n * BSTR + k] = __ushort_as_bfloat16(h);
        bl[n * BSTR + k] = __ushort_as_bfloat16(l);
    }
}

// =====================================================================
// Atoms kernel (bf16 3-term, unchanged from R12) + embedded prep CTA.
// =====================================================================
__global__ void __launch_bounds__(512, 1) atoms_kernel(
    const float* __restrict__ atom_features,
    const float* __restrict__ W_cf,
    const float* __restrict__ W_df,
    const float* __restrict__ W_fc,
    const float* __restrict__ b_cf,
    const float* __restrict__ b_df,
    float* __restrict__ out)
{
    extern __shared__ char smc[];
    const int tid = threadIdx.x;

    if (blockIdx.x == ATOM_CTAS) {
        for (int idx = tid; idx < 16384; idx += 512) {
            int n = idx >> 7, k = idx & 127;
            int o = n * BSTR + k;
            ushort_t h, l;
            float vdf = (k < N_DIST) ? W_df[k * 128 + n] : 0.0f;
            split_fp16(vdf, h, l);
            g_Bdf_h[o] = __ushort_as_half(h);
            g_Bdf_l[o] = __ushort_as_half(l);
            split_fp16(W_fc[k * 128 + n], h, l);
            g_Bfc_h[o] = __ushort_as_half(h);
            g_Bfc_l[o] = __ushort_as_half(l);
        }
        return;
    }

    float* bcf_s = (float*)(smc + ASM_IS);
    float* bdf_s = (float*)(smc + ASM_JS);
    const uint32_t sb  = smem_u32(smc);
    const uint32_t aHi = sb + ASM_AHI, aLo = sb + ASM_ALO;
    const uint32_t bHi = sb + ASM_BHI, bLo = sb + ASM_BLO;

    const int wid = tid >> 5, lane = tid & 31;
    const int rg = wid >> 2, cg = wid & 3;
    const int base  = blockIdx.x * TROWS_A;
    const int nrows = min(TROWS_A, N_ATOMS - base);

    if (tid < 128) { bcf_s[tid] = b_cf[tid]; bdf_s[tid] = b_df[tid]; }
    stage_splits_bf(smc, atom_features, base, nrows, tid);
    stage_w_direct(smc, W_cf, tid);
    __syncthreads();

    const int arow  = (lane & 7) + 8 * ((lane >> 3) & 1);
    const int acolb = 16 * (lane >> 4);
    const int brow  = (lane & 7) + 8 * (lane >> 4);
    const int bcolb = 16 * ((lane >> 3) & 1);
    const uint32_t aoff0 = (uint32_t)((rg * 64 + arow) * (BSTR * 2) + acolb);
    const uint32_t boff0 = (uint32_t)((cg * 32 + brow) * (BSTR * 2) + bcolb);

    float d[64];
#pragma unroll
    for (int i = 0; i < 64; i++) d[i] = 0.0f;
    do_gemm3<8>(aHi, aLo, bHi, bLo, aoff0, boff0, d);
    __syncthreads();

    {
        const int g = lane >> 2, tg = lane & 3;
#pragma unroll
        for (int mt = 0; mt < 4; mt++)
#pragma unroll
            for (int f2 = 0; f2 < 2; f2++) {
                const int row = rg * 64 + mt * 16 + 8 * f2 + g;
                const bool ok = row < nrows;
                char* ah = smc + ASM_AHI + row * (BSTR * 2);
                char* al = smc + ASM_ALO + row * (BSTR * 2);
                unsigned* g2 = g_afh2 + (size_t)(base + row) * N_HID;
#pragma unroll
                for (int nt = 0; nt < 4; nt++) {
                    const int c = cg * 32 + nt * 8 + 2 * tg;
                    float a0 = d[(mt*4+nt)*4 + 2*f2]     + bcf_s[c];
                    float a1 = d[(mt*4+nt)*4 + 2*f2 + 1] + bcf_s[c + 1];
                    ushort_t h0, l0, h1, l1;
                    split_bf(a0, h0, l0); split_bf(a1, h1, l1);
                    if (ok) {
                        uint2 pk;
                        pk.x = (unsigned)h0 | ((unsigned)l0 << 16);
                        pk.y = (unsigned)h1 | ((unsigned)l1 << 16);
                        *(uint2*)(g2 + c) = pk;
                    }
                    float m0 = bdf_s[c] * a0, m1 = bdf_s[c + 1] * a1;
                    split_bf(m0, h0, l0); split_bf(m1, h1, l1);
                    *(unsigned*)(ah + c * 2) = (unsigned)h0 | ((unsigned)h1 << 16);
                    *(unsigned*)(al + c * 2) = (unsigned)l0 | ((unsigned)l1 << 16);
                }
            }
    }
    stage_w_direct(smc, W_fc, tid);
    __syncthreads();

#pragma unroll
    for (int i = 0; i < 64; i++) d[i] = 0.0f;
    do_gemm3<8>(aHi, aLo, bHi, bLo, aoff0, boff0, d);

    {
        const int g = lane >> 2, tg = lane & 3;
#pragma unroll
        for (int mt = 0; mt < 4; mt++)
#pragma unroll
            for (int f2 = 0; f2 < 2; f2++) {
                const int row = rg * 64 + mt * 16 + 8 * f2 + g;
                if (row < nrows) {
                    const float* afr = atom_features + (size_t)(base + row) * N_EMB;
                    float* orow = out + (size_t)(base + row) * N_EMB;
#pragma unroll
                    for (int nt = 0; nt < 4; nt++) {
                        const int c = cg * 32 + nt * 8 + 2 * tg;
                        float2 af = *(const float2*)(afr + c);
                        float2 ov;
                        ov.x = af.x - fast_tanh(d[(mt*4+nt)*4 + 2*f2]);
                        ov.y = af.y - fast_tanh(d[(mt*4+nt)*4 + 2*f2 + 1]);
                        *(float2*)(orow + c) = ov;
                    }
                }
            }
    }
}

// =====================================================================
// Pairs kernel (fp16 2-term): 256 thr = 8 warps (2 rg x 4 cg),
// 128-pair tile, 106 KB smem -> 2 CTAs/SM for phase overlap.
// =====================================================================
__global__ void __launch_bounds__(256, 2) pairs_kernel(
    const float* __restrict__ distance,
    const int*   __restrict__ dmi,
    const int*   __restrict__ dmj,
    const float* __restrict__ b_df,
    float* __restrict__ out)
{
    extern __shared__ char smc[];
    int*   i_s   = (int*)(smc + PSM_IS);
    int*   j_s   = (int*)(smc + PSM_JS);
    float* bdf_s = (float*)(smc + PSM_BDF);
    const uint32_t sb = smem_u32(smc);
    const uint32_t aB = sb + PSM_A;
    const uint32_t bH = sb + PSM_BH, bL = sb + PSM_BL;

    const int tid = threadIdx.x;
    const int wid = tid >> 5, lane = tid & 31;
    const int rg = wid >> 2, cg = wid & 3;      // rg 0..1, cg 0..3
    const int pbase = blockIdx.x * TROWS_P;

    {
        const int srow  = tid >> 1;             // 0..127
        const int shalf = tid & 1;
        if (!shalf) {
            i_s[srow]  = dmi[pbase + srow];
            j_s[srow]  = dmj[pbase + srow];
            bdf_s[srow] = b_df[srow];
        }
    }
    stage_half(smc, distance, pbase, tid);
    for (int q = tid; q < 2176; q += 256) {
        ((uint4*)(smc + PSM_BH))[q] = ((const uint4*)g_Bdf_h)[q];
        ((uint4*)(smc + PSM_BL))[q] = ((const uint4*)g_Bdf_l)[q];
    }
    __syncthreads();

    const int arow  = (lane & 7) + 8 * ((lane >> 3) & 1);
    const int acolb = 16 * (lane >> 4);
    const int brow  = (lane & 7) + 8 * (lane >> 4);
    const int bcolb = 16 * ((lane >> 3) & 1);
    const uint32_t aoff0 = (uint32_t)((rg * 64 + arow) * (BSTR * 2) + acolb);
    const uint32_t boff0 = (uint32_t)((cg * 32 + brow) * (BSTR * 2) + bcolb);

    float d[64];
#pragma unroll
    for (int i = 0; i < 64; i++) d[i] = 0.0f;

    // GEMM1: dh = dist @ W_df (K=112 incl. zero pad)
    do_gemm2<7>(aB, bH, bL, aoff0, boff0, d);
    __syncthreads();

    // Epilogue 1: m = (dh + b_df) * afh[j] (packed gather); fp16 -> A image
    {
        const int g = lane >> 2, tg = lane & 3;
#pragma unroll
        for (int mt = 0; mt < 4; mt++)
#pragma unroll
            for (int f2 = 0; f2 < 2; f2++) {
                const int row = rg * 64 + mt * 16 + 8 * f2 + g;
                const int j = j_s[row];
                const unsigned* ar = g_afh2 + (size_t)j * N_HID;
                char* ap = smc + PSM_A + row * (BSTR * 2);
#pragma unroll
                for (int nt = 0; nt < 4; nt++) {
                    const int c = cg * 32 + nt * 8 + 2 * tg;
                    uint2 pk = *(const uint2*)(ar + c);
                    float v0 = (d[(mt*4+nt)*4 + 2*f2]     + bdf_s[c])     * unsplit(pk.x);
                    float v1 = (d[(mt*4+nt)*4 + 2*f2 + 1] + bdf_s[c + 1]) * unsplit(pk.y);
                    unsigned u = (unsigned)__half_as_ushort(__float2half_rn(v0))
                               | ((unsigned)__half_as_ushort(__float2half_rn(v1)) << 16);
                    *(unsigned*)(ap + c * 2) = u;
                }
            }
    }
    for (int q = tid; q < 2176; q += 256) {
        ((uint4*)(smc + PSM_BH))[q] = ((const uint4*)g_Bfc_h)[q];
        ((uint4*)(smc + PSM_BL))[q] = ((const uint4*)g_Bfc_l)[q];
    }
    __syncthreads();

    // GEMM2: pre = m @ W_fc (K=128)
#pragma unroll
    for (int i = 0; i < 64; i++) d[i] = 0.0f;
    do_gemm2<8>(aB, bH, bL, aoff0, boff0, d);
    __syncthreads();

    // Epilogue 2: msg = tanh(pre) -> fp32, overlays A + BH regions
    {
        float* msg = (float*)(smc + PSM_MSG);
        const int g = lane >> 2, tg = lane & 3;
#pragma unroll
        for (int mt = 0; mt < 4; mt++)
#pragma unroll
            for (int f2 = 0; f2 < 2; f2++) {
                const int row = rg * 64 + mt * 16 + 8 * f2 + g;
#pragma unroll
                for (int nt = 0; nt < 4; nt++) {
                    const int c = cg * 32 + nt * 8 + 2 * tg;
                    msg[row * 129 + c]     = fast_tanh(d[(mt*4+nt)*4 + 2*f2]);
                    msg[row * 129 + c + 1] = fast_tanh(d[(mt*4+nt)*4 + 2*f2 + 1]);
                }
            }
    }
    __syncthreads();

    // Segment sum over sorted i: 256 thr = 128 cols x 2 halves
    {
        const float* msg = (const float*)(smc + PSM_MSG);
        const int c  = tid & 127;
        const int h0 = (tid >> 7) * 64;      // 0 or 64
        int   cur = i_s[h0];
        float sum = 0.0f;
        for (int rr = h0; rr < h0 + 64; rr++) {
            int ii = i_s[rr];
            if (ii != cur) {
                atomicAdd(out + (size_t)cur * N_EMB + c, sum);
                cur = ii; sum = 0.0f;
            }
            sum += msg[rr * 129 + c];
        }
        atomicAdd(out + (size_t)cur * N_EMB + c, sum);
    }
}

// =====================================================================
extern "C" void kernel_launch(void* const* d_in, const int* in_sizes, int n_in,
                              void* d_out, int out_size)
{
    const float* atom_features = (const float*)d_in[0];
    const float* distance      = (const float*)d_in[1];
    const int*   dmi           = (const int*)d_in[3];
    const int*   dmj           = (const int*)d_in[4];
    const float* W_cf          = (const float*)d_in[5];
    const float* W_df          = (const float*)d_in[6];
    const float* W_fc          = (const float*)d_in[7];
    const float* b_cf          = (const float*)d_in[8];
    const float* b_df          = (const float*)d_in[9];
    float*       out           = (float*)d_out;

    cudaFuncSetAttribute(atoms_kernel, cudaFuncAttributeMaxDynamicSharedMemorySize, ASM_TOTAL);
    cudaFuncSetAttribute(pairs_kernel, cudaFuncAttributeMaxDynamicSharedMemorySize, PSM_TOTAL);

    atoms_kernel<<<ATOM_CTAS + 1, 512, ASM_TOTAL>>>(
        atom_features, W_cf, W_df, W_fc, b_cf, b_df, out);
    pairs_kernel<<<N_PAIRS / TROWS_P, 256, PSM_TOTAL>>>(
        distance, dmi, dmj, b_df, out);
}

// round 14
// speedup vs baseline: 1.3909x; 1.3909x over previous
#include <cuda_runtime.h>
#include <cuda_bf16.h>
#include <cuda_fp16.h>
#include <cstdint>

#define N_ATOMS 50000
#define N_PAIRS 800000
#define N_EMB   128
#define N_DIST  100
#define N_HID   128
#define BSTR    136          // padded element row stride (272 B for 2B types)
#define TROWS   256          // rows per CTA tile (pairs & atoms)
#define ATOM_CTAS ((N_ATOMS + TROWS - 1) / TROWS)   // 196

typedef unsigned long long ull;
typedef unsigned short ushort_t;

// ---------------- device scratch ----------------
__device__ __align__(16) unsigned g_afh2[(size_t)N_ATOMS * N_HID];
// single fp16 images of W_df^T / W_fc^T for the pairs kernel
__device__ __align__(16) __half g_Bdf_h[128 * BSTR];
__device__ __align__(16) __half g_Bfc_h[128 * BSTR];

// ---------------- helpers ----------------
static __device__ __forceinline__ float fast_tanh(float x) {
    float e = __expf(2.0f * x);
    return 1.0f - __fdividef(2.0f, e + 1.0f);
}
static __device__ __forceinline__ void split_bf(float x, ushort_t &h, ushort_t &l) {
    __nv_bfloat16 bh = __float2bfloat16(x);
    float r = x - __bfloat162float(bh);
    __nv_bfloat16 bl = __float2bfloat16(r);
    h = __bfloat16_as_ushort(bh);
    l = __bfloat16_as_ushort(bl);
}
static __device__ __forceinline__ float unsplit(unsigned p) {
    return __bfloat162float(__ushort_as_bfloat16((ushort_t)(p & 0xFFFF)))
         + __bfloat162float(__ushort_as_bfloat16((ushort_t)(p >> 16)));
}
static __device__ __forceinline__ uint32_t smem_u32(const void* p) {
    uint32_t a;
    asm("{ .reg .u64 t; cvta.to.shared.u64 t, %1; cvt.u32.u64 %0, t; }"
        : "=r"(a) : "l"(p));
    return a;
}
static __device__ __forceinline__ void ldsm4(uint32_t* r, uint32_t addr) {
    asm volatile("ldmatrix.sync.aligned.m8n8.x4.shared.b16 {%0,%1,%2,%3}, [%4];"
                 : "=r"(r[0]), "=r"(r[1]), "=r"(r[2]), "=r"(r[3]) : "r"(addr));
}
static __device__ __forceinline__ void mma_bf16(float* d, const uint32_t* a,
                                                const uint32_t* b) {
    asm volatile(
        "mma.sync.aligned.m16n8k16.row.col.f32.bf16.bf16.f32 "
        "{%0,%1,%2,%3}, {%4,%5,%6,%7}, {%8,%9}, {%0,%1,%2,%3};"
        : "+f"(d[0]), "+f"(d[1]), "+f"(d[2]), "+f"(d[3])
        : "r"(a[0]), "r"(a[1]), "r"(a[2]), "r"(a[3]), "r"(b[0]), "r"(b[1]));
}
static __device__ __forceinline__ void mma_f16(float* d, const uint32_t* a,
                                               const uint32_t* b) {
    asm volatile(
        "mma.sync.aligned.m16n8k16.row.col.f32.f16.f16.f32 "
        "{%0,%1,%2,%3}, {%4,%5,%6,%7}, {%8,%9}, {%0,%1,%2,%3};"
        : "+f"(d[0]), "+f"(d[1]), "+f"(d[2]), "+f"(d[3])
        : "r"(a[0]), "r"(a[1]), "r"(a[2]), "r"(a[3]), "r"(b[0]), "r"(b[1]));
}

// ---------------- atoms kernel SMEM layout (bf16 3-term, as R12) ---------
#define ASM_IS    0
#define ASM_JS    1024
#define ASM_AHI   2560
#define ASM_ALO   (ASM_AHI + 69632)
#define ASM_BHI   (ASM_ALO + 69632)
#define ASM_BLO   (ASM_BHI + 34816)
#define ASM_TOTAL (ASM_BLO + 34816)        // 211456 B

// ---------------- pairs kernel SMEM layout (fp16 1-term, both W) ---------
#define PSM_IS    0                        // 256 int
#define PSM_JS    1024                     // 256 int
#define PSM_BDF   2048                     // 128 float
#define PSM_A     2560                     // 256 x 136 fp16 = 69632 B
#define PSM_WDF   (PSM_A + 69632)          // 72192  (34816 B)
#define PSM_WFC   (PSM_WDF + 34816)        // 107008 (34816 B)
#define PSM_TOTAL (PSM_WFC + 34816)        // 141824 B
#define PSM_MSG   PSM_A                    // fp32 msg 256x129 = 132096 B,
                                           // overlays A+WDF+WFC (dead post-GEMM2)

// =====================================================================
// Warp GEMM, bf16 3-term (atoms): D[256,128], 16 warps, warp tile 64x32.
// =====================================================================
template<int KSTEPS>
static __device__ __forceinline__ void do_gemm3(
    uint32_t aHi, uint32_t aLo, uint32_t bHi, uint32_t bLo,
    uint32_t aoff0, uint32_t boff0, float* d)
{
#pragma unroll 1
    for (int ks = 0; ks < KSTEPS; ks++) {
        uint32_t Ah[4][4], Al[4][4], Bh[4][2], Bl[4][2];
#pragma unroll
        for (int mt = 0; mt < 4; mt++) {
            uint32_t off = aoff0 + mt * (16 * BSTR * 2) + ks * 32;
            ldsm4(Ah[mt], aHi + off);
            ldsm4(Al[mt], aLo + off);
        }
#pragma unroll
        for (int np = 0; np < 2; np++) {
            uint32_t off = boff0 + np * (16 * BSTR * 2) + ks * 32;
            uint32_t th[4], tl[4];
            ldsm4(th, bHi + off);
            ldsm4(tl, bLo + off);
            Bh[2*np][0] = th[0]; Bh[2*np][1] = th[1];
            Bh[2*np+1][0] = th[2]; Bh[2*np+1][1] = th[3];
            Bl[2*np][0] = tl[0]; Bl[2*np][1] = tl[1];
            Bl[2*np+1][0] = tl[2]; Bl[2*np+1][1] = tl[3];
        }
#pragma unroll
        for (int mt = 0; mt < 4; mt++)
#pragma unroll
            for (int nt = 0; nt < 4; nt++) {
                float* dd = d + (mt * 4 + nt) * 4;
                mma_bf16(dd, Ah[mt], Bh[nt]);
                mma_bf16(dd, Ah[mt], Bl[nt]);
                mma_bf16(dd, Al[mt], Bh[nt]);
            }
    }
}

// =====================================================================
// Warp GEMM, fp16 1-term (pairs): plain fp16 HMMA, A and B single images.
// 6 LDSM + 16 MMA per kstep per warp.
// =====================================================================
template<int KSTEPS>
static __device__ __forceinline__ void do_gemm1t(
    uint32_t aBase, uint32_t bBase,
    uint32_t aoff0, uint32_t boff0, float* d)
{
#pragma unroll 1
    for (int ks = 0; ks < KSTEPS; ks++) {
        uint32_t Ah[4][4], B[4][2];
#pragma unroll
        for (int mt = 0; mt < 4; mt++) {
            uint32_t off = aoff0 + mt * (16 * BSTR * 2) + ks * 32;
            ldsm4(Ah[mt], aBase + off);
        }
#pragma unroll
        for (int np = 0; np < 2; np++) {
            uint32_t off = boff0 + np * (16 * BSTR * 2) + ks * 32;
            uint32_t t[4];
            ldsm4(t, bBase + off);
            B[2*np][0] = t[0]; B[2*np][1] = t[1];
            B[2*np+1][0] = t[2]; B[2*np+1][1] = t[3];
        }
#pragma unroll
        for (int mt = 0; mt < 4; mt++)
#pragma unroll
            for (int nt = 0; nt < 4; nt++)
                mma_f16(d + (mt * 4 + nt) * 4, Ah[mt], B[nt]);
    }
}

// ======== staging helpers ========
static __device__ __forceinline__ void stage_splits_bf(
    char* smc, const float* __restrict__ src, int base, int nrows, int tid)
{
    const int srow  = tid >> 1;
    const int shalf = tid & 1;
    const int q0 = shalf ? 16 : 0;
    const int q1 = shalf ? 32 : 16;
    char* ah = smc + ASM_AHI + srow * (BSTR * 2);
    char* al = smc + ASM_ALO + srow * (BSTR * 2);
    if (srow < nrows) {
        const float4* dr = (const float4*)(src + (size_t)(base + srow) * 128);
#pragma unroll
        for (int q = q0; q < q1; q++) {
            float4 v = dr[q];
            ushort_t h0,l0,h1,l1,h2,l2,h3,l3;
            split_bf(v.x, h0, l0); split_bf(v.y, h1, l1);
            split_bf(v.z, h2, l2); split_bf(v.w, h3, l3);
            *(unsigned*)(ah + 8 * q)     = (unsigned)h0 | ((unsigned)h1 << 16);
            *(unsigned*)(ah + 8 * q + 4) = (unsigned)h2 | ((unsigned)h3 << 16);
            *(unsigned*)(al + 8 * q)     = (unsigned)l0 | ((unsigned)l1 << 16);
            *(unsigned*)(al + 8 * q + 4) = (unsigned)l2 | ((unsigned)l3 << 16);
        }
    } else {
        for (int q = q0; q < q1; q++) {
            *(ull*)(ah + 8 * q) = 0ULL;
            *(ull*)(al + 8 * q) = 0ULL;
        }
    }
}
// fp16 single-image staging of distance (2 threads per row)
static __device__ __forceinline__ void stage_half(
    char* smc, const float* __restrict__ src, int base, int tid)
{
    const int srow  = tid >> 1;
    const int shalf = tid & 1;
    const int q0 = shalf ? 13 : 0;
    const int q1 = shalf ? 25 : 13;
    char* ap = smc + PSM_A + srow * (BSTR * 2);
    const float4* dr = (const float4*)(src + (size_t)(base + srow) * N_DIST);
#pragma unroll
    for (int q = q0; q < q1; q++) {
        float4 v = dr[q];
        unsigned u01 = (unsigned)__half_as_ushort(__float2half_rn(v.x))
                     | ((unsigned)__half_as_ushort(__float2half_rn(v.y)) << 16);
        unsigned u23 = (unsigned)__half_as_ushort(__float2half_rn(v.z))
                     | ((unsigned)__half_as_ushort(__float2half_rn(v.w)) << 16);
        *(unsigned*)(ap + 8 * q)     = u01;
        *(unsigned*)(ap + 8 * q + 4) = u23;
    }
    if (shalf) {
#pragma unroll
        for (int c = 100; c < 112; c += 2)   // zero pad for kstep 6
            *(unsigned*)(ap + c * 2) = 0u;
    }
}
static __device__ __forceinline__ void stage_w_direct(
    char* smc, const float* __restrict__ W, int tid)
{
    __nv_bfloat16* bh = (__nv_bfloat16*)(smc + ASM_BHI);
    __nv_bfloat16* bl = (__nv_bfloat16*)(smc + ASM_BLO);
    for (int idx = tid; idx < 16384; idx += 512) {
        int k = idx >> 7, n = idx & 127;
        ushort_t h, l;
        split_bf(W[idx], h, l);
        bh[n * BSTR + k] = __ushort_as_bfloat16(h);
        bl[n * BSTR + k] = __ushort_as_bfloat16(l);
    }
}

// =====================================================================
// Atoms kernel (bf16 3-term, unchanged from R12) + embedded prep CTA
// that builds the pairs kernel's single fp16 W images.
// =====================================================================
__global__ void __launch_bounds__(512, 1) atoms_kernel(
    const float* __restrict__ atom_features,
    const float* __restrict__ W_cf,
    const float* __restrict__ W_df,
    const float* __restrict__ W_fc,
    const float* __restrict__ b_cf,
    const float* __restrict__ b_df,
    float* __restrict__ out)
{
    extern __shared__ char smc[];
    const int tid = threadIdx.x;

    if (blockIdx.x == ATOM_CTAS) {
        for (int idx = tid; idx < 16384; idx += 512) {
            int n = idx >> 7, k = idx & 127;
            int o = n * BSTR + k;
            float vdf = (k < N_DIST) ? W_df[k * 128 + n] : 0.0f;
            g_Bdf_h[o] = __float2half_rn(vdf);
            g_Bfc_h[o] = __float2half_rn(W_fc[k * 128 + n]);
        }
        return;
    }

    float* bcf_s = (float*)(smc + ASM_IS);
    float* bdf_s = (float*)(smc + ASM_JS);
    const uint32_t sb  = smem_u32(smc);
    const uint32_t aHi = sb + ASM_AHI, aLo = sb + ASM_ALO;
    const uint32_t bHi = sb + ASM_BHI, bLo = sb + ASM_BLO;

    const int wid = tid >> 5, lane = tid & 31;
    const int rg = wid >> 2, cg = wid & 3;
    const int base  = blockIdx.x * TROWS;
    const int nrows = min(TROWS, N_ATOMS - base);

    if (tid < 128) { bcf_s[tid] = b_cf[tid]; bdf_s[tid] = b_df[tid]; }
    stage_splits_bf(smc, atom_features, base, nrows, tid);
    stage_w_direct(smc, W_cf, tid);
    __syncthreads();

    const int arow  = (lane & 7) + 8 * ((lane >> 3) & 1);
    const int acolb = 16 * (lane >> 4);
    const int brow  = (lane & 7) + 8 * (lane >> 4);
    const int bcolb = 16 * ((lane >> 3) & 1);
    const uint32_t aoff0 = (uint32_t)((rg * 64 + arow) * (BSTR * 2) + acolb);
    const uint32_t boff0 = (uint32_t)((cg * 32 + brow) * (BSTR * 2) + bcolb);

    float d[64];
#pragma unroll
    for (int i = 0; i < 64; i++) d[i] = 0.0f;
    do_gemm3<8>(aHi, aLo, bHi, bLo, aoff0, boff0, d);
    __syncthreads();

    {
        const int g = lane >> 2, tg = lane & 3;
#pragma unroll
        for (int mt = 0; mt < 4; mt++)
#pragma unroll
            for (int f2 = 0; f2 < 2; f2++) {
                const int row = rg * 64 + mt * 16 + 8 * f2 + g;
                const bool ok = row < nrows;
                char* ah = smc + ASM_AHI + row * (BSTR * 2);
                char* al = smc + ASM_ALO + row * (BSTR * 2);
                unsigned* g2 = g_afh2 + (size_t)(base + row) * N_HID;
#pragma unroll
                for (int nt = 0; nt < 4; nt++) {
                    const int c = cg * 32 + nt * 8 + 2 * tg;
                    float a0 = d[(mt*4+nt)*4 + 2*f2]     + bcf_s[c];
                    float a1 = d[(mt*4+nt)*4 + 2*f2 + 1] + bcf_s[c + 1];
                    ushort_t h0, l0, h1, l1;
                    split_bf(a0, h0, l0); split_bf(a1, h1, l1);
                    if (ok) {
                        uint2 pk;
                        pk.x = (unsigned)h0 | ((unsigned)l0 << 16);
                        pk.y = (unsigned)h1 | ((unsigned)l1 << 16);
                        *(uint2*)(g2 + c) = pk;
                    }
                    float m0 = bdf_s[c] * a0, m1 = bdf_s[c + 1] * a1;
                    split_bf(m0, h0, l0); split_bf(m1, h1, l1);
                    *(unsigned*)(ah + c * 2) = (unsigned)h0 | ((unsigned)h1 << 16);
                    *(unsigned*)(al + c * 2) = (unsigned)l0 | ((unsigned)l1 << 16);
                }
            }
    }
    stage_w_direct(smc, W_fc, tid);
    __syncthreads();

#pragma unroll
    for (int i = 0; i < 64; i++) d[i] = 0.0f;
    do_gemm3<8>(aHi, aLo, bHi, bLo, aoff0, boff0, d);

    {
        const int g = lane >> 2, tg = lane & 3;
#pragma unroll
        for (int mt = 0; mt < 4; mt++)
#pragma unroll
            for (int f2 = 0; f2 < 2; f2++) {
                const int row = rg * 64 + mt * 16 + 8 * f2 + g;
                if (row < nrows) {
                    const float* afr = atom_features + (size_t)(base + row) * N_EMB;
                    float* orow = out + (size_t)(base + row) * N_EMB;
#pragma unroll
                    for (int nt = 0; nt < 4; nt++) {
                        const int c = cg * 32 + nt * 8 + 2 * tg;
                        float2 af = *(const float2*)(afr + c);
                        float2 ov;
                        ov.x = af.x - fast_tanh(d[(mt*4+nt)*4 + 2*f2]);
                        ov.y = af.y - fast_tanh(d[(mt*4+nt)*4 + 2*f2 + 1]);
                        *(float2*)(orow + c) = ov;
                    }
                }
            }
    }
}

// =====================================================================
// Pairs kernel (fp16 1-term, both W resident): 512 thr = 16 warps,
// 256-pair tile, no mid-kernel W copy.
// =====================================================================
__global__ void __launch_bounds__(512, 1) pairs_kernel(
    const float* __restrict__ distance,
    const int*   __restrict__ dmi,
    const int*   __restrict__ dmj,
    const float* __restrict__ b_df,
    float* __restrict__ out)
{
    extern __shared__ char smc[];
    int*   i_s   = (int*)(smc + PSM_IS);
    int*   j_s   = (int*)(smc + PSM_JS);
    float* bdf_s = (float*)(smc + PSM_BDF);
    const uint32_t sb = smem_u32(smc);
    const uint32_t aB  = sb + PSM_A;
    const uint32_t wDF = sb + PSM_WDF;
    const uint32_t wFC = sb + PSM_WFC;

    const int tid = threadIdx.x;
    const int wid = tid >> 5, lane = tid & 31;
    const int rg = wid >> 2, cg = wid & 3;
    const int pbase = blockIdx.x * TROWS;

    {
        const int srow  = tid >> 1;
        const int shalf = tid & 1;
        if (!shalf) {
            i_s[srow]  = dmi[pbase + srow];
            j_s[srow]  = dmj[pbase + srow];
            if (srow < 128) bdf_s[srow] = b_df[srow];
        }
    }
    stage_half(smc, distance, pbase, tid);
    for (int q = tid; q < 2176; q += 512) {
        ((uint4*)(smc + PSM_WDF))[q] = ((const uint4*)g_Bdf_h)[q];
        ((uint4*)(smc + PSM_WFC))[q] = ((const uint4*)g_Bfc_h)[q];
    }
    __syncthreads();

    const int arow  = (lane & 7) + 8 * ((lane >> 3) & 1);
    const int acolb = 16 * (lane >> 4);
    const int brow  = (lane & 7) + 8 * (lane >> 4);
    const int bcolb = 16 * ((lane >> 3) & 1);
    const uint32_t aoff0 = (uint32_t)((rg * 64 + arow) * (BSTR * 2) + acolb);
    const uint32_t boff0 = (uint32_t)((cg * 32 + brow) * (BSTR * 2) + bcolb);

    float d[64];
#pragma unroll
    for (int i = 0; i < 64; i++) d[i] = 0.0f;

    // GEMM1: dh = dist @ W_df (K=112 incl. zero pad)
    do_gemm1t<7>(aB, wDF, aoff0, boff0, d);
    __syncthreads();   // GEMM1's A reads done before epi1 overwrites A

    // Epilogue 1: m = (dh + b_df) * afh[j] (packed gather); fp16 -> A image
    {
        const int g = lane >> 2, tg = lane & 3;
#pragma unroll
        for (int mt = 0; mt < 4; mt++)
#pragma unroll
            for (int f2 = 0; f2 < 2; f2++) {
                const int row = rg * 64 + mt * 16 + 8 * f2 + g;
                const int j = j_s[row];
                const unsigned* ar = g_afh2 + (size_t)j * N_HID;
                char* ap = smc + PSM_A + row * (BSTR * 2);
#pragma unroll
                for (int nt = 0; nt < 4; nt++) {
                    const int c = cg * 32 + nt * 8 + 2 * tg;
                    uint2 pk = *(const uint2*)(ar + c);
                    float v0 = (d[(mt*4+nt)*4 + 2*f2]     + bdf_s[c])     * unsplit(pk.x);
                    float v1 = (d[(mt*4+nt)*4 + 2*f2 + 1] + bdf_s[c + 1]) * unsplit(pk.y);
                    unsigned u = (unsigned)__half_as_ushort(__float2half_rn(v0))
                               | ((unsigned)__half_as_ushort(__float2half_rn(v1)) << 16);
                    *(unsigned*)(ap + c * 2) = u;
                }
            }
    }
    __syncthreads();

    // GEMM2: pre = m @ W_fc (K=128)
#pragma unroll
    for (int i = 0; i < 64; i++) d[i] = 0.0f;
    do_gemm1t<8>(aB, wFC, aoff0, boff0, d);
    __syncthreads();

    // Epilogue 2: msg = tanh(pre) -> fp32, overlays A+W regions
    {
        float* msg = (float*)(smc + PSM_MSG);
        const int g = lane >> 2, tg = lane & 3;
#pragma unroll
        for (int mt = 0; mt < 4; mt++)
#pragma unroll
            for (int f2 = 0; f2 < 2; f2++) {
                const int row = rg * 64 + mt * 16 + 8 * f2 + g;
#pragma unroll
                for (int nt = 0; nt < 4; nt++) {
                    const int c = cg * 32 + nt * 8 + 2 * tg;
                    msg[row * 129 + c]     = fast_tanh(d[(mt*4+nt)*4 + 2*f2]);
                    msg[row * 129 + c + 1] = fast_tanh(d[(mt*4+nt)*4 + 2*f2 + 1]);
                }
            }
    }
    __syncthreads();

    // Segment sum over sorted i: 512 thr = 128 cols x 4 quarters
    {
        const float* msg = (const float*)(smc + PSM_MSG);
        const int c  = tid & 127;
        const int h0 = (tid >> 7) * 64;
        int   cur = i_s[h0];
        float sum = 0.0f;
        for (int rr = h0; rr < h0 + 64; rr++) {
            int ii = i_s[rr];
            if (ii != cur) {
                atomicAdd(out + (size_t)cur * N_EMB + c, sum);
                cur = ii; sum = 0.0f;
            }
            sum += msg[rr * 129 + c];
        }
        atomicAdd(out + (size_t)cur * N_EMB + c, sum);
    }
}

// =====================================================================
extern "C" void kernel_launch(void* const* d_in, const int* in_sizes, int n_in,
                              void* d_out, int out_size)
{
    const float* atom_features = (const float*)d_in[0];
    const float* distance      = (const float*)d_in[1];
    const int*   dmi           = (const int*)d_in[3];
    const int*   dmj           = (const int*)d_in[4];
    const float* W_cf          = (const float*)d_in[5];
    const float* W_df          = (const float*)d_in[6];
    const float* W_fc          = (const float*)d_in[7];
    const float* b_cf          = (const float*)d_in[8];
    const float* b_df          = (const float*)d_in[9];
    float*       out           = (float*)d_out;

    cudaFuncSetAttribute(atoms_kernel, cudaFuncAttributeMaxDynamicSharedMemorySize, ASM_TOTAL);
    cudaFuncSetAttribute(pairs_kernel, cudaFuncAttributeMaxDynamicSharedMemorySize, PSM_TOTAL);

    atoms_kernel<<<ATOM_CTAS + 1, 512, ASM_TOTAL>>>(
        atom_features, W_cf, W_df, W_fc, b_cf, b_df, out);
    pairs_kernel<<<N_PAIRS / TROWS, 512, PSM_TOTAL>>>(
        distance, dmi, dmj, b_df, out);
}

// round 15
// speedup vs baseline: 1.5155x; 1.0896x over previous
#include <cuda_runtime.h>
#include <cuda_bf16.h>
#include <cuda_fp16.h>
#include <cstdint>

#define N_ATOMS 50000
#define N_PAIRS 800000
#define N_EMB   128
#define N_DIST  100
#define N_HID   128
#define BSTR    136          // padded element row stride (272 B for 2B types)
#define TROWS   256          // rows per CTA tile (pairs & atoms)
#define ATOM_CTAS ((N_ATOMS + TROWS - 1) / TROWS)   // 196

typedef unsigned long long ull;
typedef unsigned short ushort_t;

// ---------------- device scratch ----------------
__device__ __align__(16) float g_afh[(size_t)N_ATOMS * N_HID];   // fp32, 25.6MB
__device__ __align__(16) __half g_Bdf_h[128 * BSTR];
__device__ __align__(16) __half g_Bfc_h[128 * BSTR];

// ---------------- helpers ----------------
static __device__ __forceinline__ float tanh_approx(float x) {
    float y;
    asm("tanh.approx.f32 %0, %1;" : "=f"(y) : "f"(x));
    return y;
}
static __device__ __forceinline__ void split_bf(float x, ushort_t &h, ushort_t &l) {
    __nv_bfloat16 bh = __float2bfloat16(x);
    float r = x - __bfloat162float(bh);
    __nv_bfloat16 bl = __float2bfloat16(r);
    h = __bfloat16_as_ushort(bh);
    l = __bfloat16_as_ushort(bl);
}
static __device__ __forceinline__ uint32_t smem_u32(const void* p) {
    uint32_t a;
    asm("{ .reg .u64 t; cvta.to.shared.u64 t, %1; cvt.u32.u64 %0, t; }"
        : "=r"(a) : "l"(p));
    return a;
}
static __device__ __forceinline__ void ldsm4(uint32_t* r, uint32_t addr) {
    asm volatile("ldmatrix.sync.aligned.m8n8.x4.shared.b16 {%0,%1,%2,%3}, [%4];"
                 : "=r"(r[0]), "=r"(r[1]), "=r"(r[2]), "=r"(r[3]) : "r"(addr));
}
static __device__ __forceinline__ void mma_bf16(float* d, const uint32_t* a,
                                                const uint32_t* b) {
    asm volatile(
        "mma.sync.aligned.m16n8k16.row.col.f32.bf16.bf16.f32 "
        "{%0,%1,%2,%3}, {%4,%5,%6,%7}, {%8,%9}, {%0,%1,%2,%3};"
        : "+f"(d[0]), "+f"(d[1]), "+f"(d[2]), "+f"(d[3])
        : "r"(a[0]), "r"(a[1]), "r"(a[2]), "r"(a[3]), "r"(b[0]), "r"(b[1]));
}
static __device__ __forceinline__ void mma_f16(float* d, const uint32_t* a,
                                               const uint32_t* b) {
    asm volatile(
        "mma.sync.aligned.m16n8k16.row.col.f32.f16.f16.f32 "
        "{%0,%1,%2,%3}, {%4,%5,%6,%7}, {%8,%9}, {%0,%1,%2,%3};"
        : "+f"(d[0]), "+f"(d[1]), "+f"(d[2]), "+f"(d[3])
        : "r"(a[0]), "r"(a[1]), "r"(a[2]), "r"(a[3]), "r"(b[0]), "r"(b[1]));
}
#define RG_BAR(rg) asm volatile("bar.sync %0, %1;" :: "r"((rg) + 1), "r"(128) : "memory")

// ---------------- atoms kernel SMEM layout (bf16 3-term) -----------------
#define ASM_IS    0
#define ASM_JS    1024
#define ASM_AHI   2560
#define ASM_ALO   (ASM_AHI + 69632)
#define ASM_BHI   (ASM_ALO + 69632)
#define ASM_BLO   (ASM_BHI + 34816)
#define ASM_TOTAL (ASM_BLO + 34816)        // 211456 B

// ---------------- pairs kernel SMEM layout (fp16 1-term, both W) ---------
#define PSM_IS    0                        // 256 int
#define PSM_JS    1024                     // 256 int
#define PSM_BDF   2048                     // 128 float
#define PSM_A     2560                     // 256 x 136 fp16 = 69632 B
#define PSM_WDF   (PSM_A + 69632)          // 72192  (34816 B)
#define PSM_WFC   (PSM_WDF + 34816)        // 107008 (34816 B)
#define PSM_TOTAL (PSM_WFC + 34816)        // 141824 B
// msg (fp16) is stored in-place in each rg's own A-quarter (stride 136)

// =====================================================================
// Warp GEMM, bf16 3-term (atoms): D[256,128], 16 warps, warp tile 64x32.
// =====================================================================
template<int KSTEPS>
static __device__ __forceinline__ void do_gemm3(
    uint32_t aHi, uint32_t aLo, uint32_t bHi, uint32_t bLo,
    uint32_t aoff0, uint32_t boff0, float* d)
{
#pragma unroll 1
    for (int ks = 0; ks < KSTEPS; ks++) {
        uint32_t Ah[4][4], Al[4][4], Bh[4][2], Bl[4][2];
#pragma unroll
        for (int mt = 0; mt < 4; mt++) {
            uint32_t off = aoff0 + mt * (16 * BSTR * 2) + ks * 32;
            ldsm4(Ah[mt], aHi + off);
            ldsm4(Al[mt], aLo + off);
        }
#pragma unroll
        for (int np = 0; np < 2; np++) {
            uint32_t off = boff0 + np * (16 * BSTR * 2) + ks * 32;
            uint32_t th[4], tl[4];
            ldsm4(th, bHi + off);
            ldsm4(tl, bLo + off);
            Bh[2*np][0] = th[0]; Bh[2*np][1] = th[1];
            Bh[2*np+1][0] = th[2]; Bh[2*np+1][1] = th[3];
            Bl[2*np][0] = tl[0]; Bl[2*np][1] = tl[1];
            Bl[2*np+1][0] = tl[2]; Bl[2*np+1][1] = tl[3];
        }
#pragma unroll
        for (int mt = 0; mt < 4; mt++)
#pragma unroll
            for (int nt = 0; nt < 4; nt++) {
                float* dd = d + (mt * 4 + nt) * 4;
                mma_bf16(dd, Ah[mt], Bh[nt]);
                mma_bf16(dd, Ah[mt], Bl[nt]);
                mma_bf16(dd, Al[mt], Bh[nt]);
            }
    }
}

// =====================================================================
// Warp GEMM, fp16 1-term (pairs): 6 LDSM + 16 MMA per kstep per warp.
// =====================================================================
template<int KSTEPS>
static __device__ __forceinline__ void do_gemm1t(
    uint32_t aBase, uint32_t bBase,
    uint32_t aoff0, uint32_t boff0, float* d)
{
#pragma unroll 1
    for (int ks = 0; ks < KSTEPS; ks++) {
        uint32_t Ah[4][4], B[4][2];
#pragma unroll
        for (int mt = 0; mt < 4; mt++) {
            uint32_t off = aoff0 + mt * (16 * BSTR * 2) + ks * 32;
            ldsm4(Ah[mt], aBase + off);
        }
#pragma unroll
        for (int np = 0; np < 2; np++) {
            uint32_t off = boff0 + np * (16 * BSTR * 2) + ks * 32;
            uint32_t t[4];
            ldsm4(t, bBase + off);
            B[2*np][0] = t[0]; B[2*np][1] = t[1];
            B[2*np+1][0] = t[2]; B[2*np+1][1] = t[3];
        }
#pragma unroll
        for (int mt = 0; mt < 4; mt++)
#pragma unroll
            for (int nt = 0; nt < 4; nt++)
                mma_f16(d + (mt * 4 + nt) * 4, Ah[mt], B[nt]);
    }
}

// ======== staging helpers ========
static __device__ __forceinline__ void stage_splits_bf(
    char* smc, const float* __restrict__ src, int base, int nrows, int tid)
{
    const int srow  = tid >> 1;
    const int shalf = tid & 1;
    const int q0 = shalf ? 16 : 0;
    const int q1 = shalf ? 32 : 16;
    char* ah = smc + ASM_AHI + srow * (BSTR * 2);
    char* al = smc + ASM_ALO + srow * (BSTR * 2);
    if (srow < nrows) {
        const float4* dr = (const float4*)(src + (size_t)(base + srow) * 128);
#pragma unroll
        for (int q = q0; q < q1; q++) {
            float4 v = dr[q];
            ushort_t h0,l0,h1,l1,h2,l2,h3,l3;
            split_bf(v.x, h0, l0); split_bf(v.y, h1, l1);
            split_bf(v.z, h2, l2); split_bf(v.w, h3, l3);
            *(unsigned*)(ah + 8 * q)     = (unsigned)h0 | ((unsigned)h1 << 16);
            *(unsigned*)(ah + 8 * q + 4) = (unsigned)h2 | ((unsigned)h3 << 16);
            *(unsigned*)(al + 8 * q)     = (unsigned)l0 | ((unsigned)l1 << 16);
            *(unsigned*)(al + 8 * q + 4) = (unsigned)l2 | ((unsigned)l3 << 16);
        }
    } else {
        for (int q = q0; q < q1; q++) {
            *(ull*)(ah + 8 * q) = 0ULL;
            *(ull*)(al + 8 * q) = 0ULL;
        }
    }
}
static __device__ __forceinline__ void stage_half(
    char* smc, const float* __restrict__ src, int base, int tid)
{
    const int srow  = tid >> 1;
    const int shalf = tid & 1;
    const int q0 = shalf ? 13 : 0;
    const int q1 = shalf ? 25 : 13;
    char* ap = smc + PSM_A + srow * (BSTR * 2);
    const float4* dr = (const float4*)(src + (size_t)(base + srow) * N_DIST);
#pragma unroll
    for (int q = q0; q < q1; q++) {
        float4 v = dr[q];
        unsigned u01 = (unsigned)__half_as_ushort(__float2half_rn(v.x))
                     | ((unsigned)__half_as_ushort(__float2half_rn(v.y)) << 16);
        unsigned u23 = (unsigned)__half_as_ushort(__float2half_rn(v.z))
                     | ((unsigned)__half_as_ushort(__float2half_rn(v.w)) << 16);
        *(unsigned*)(ap + 8 * q)     = u01;
        *(unsigned*)(ap + 8 * q + 4) = u23;
    }
    if (shalf) {
#pragma unroll
        for (int c = 100; c < 112; c += 2)   // zero pad for kstep 6
            *(unsigned*)(ap + c * 2) = 0u;
    }
}
static __device__ __forceinline__ void stage_w_direct(
    char* smc, const float* __restrict__ W, int tid)
{
    __nv_bfloat16* bh = (__nv_bfloat16*)(smc + ASM_BHI);
    __nv_bfloat16* bl = (__nv_bfloat16*)(smc + ASM_BLO);
    for (int idx = tid; idx < 16384; idx += 512) {
        int k = idx >> 7, n = idx & 127;
        ushort_t h, l;
        split_bf(W[idx], h, l);
        bh[n * BSTR + k] = __ushort_as_bfloat16(h);
        bl[n * BSTR + k] = __ushort_as_bfloat16(l);
    }
}

// =====================================================================
// Atoms kernel (bf16 3-term) + embedded prep CTA (fp16 W images).
//   afh = A @ W_cf + b_cf -> g_afh (fp32)
//   out = A - tanh((b_df*afh) @ W_fc)
// =====================================================================
__global__ void __launch_bounds__(512, 1) atoms_kernel(
    const float* __restrict__ atom_features,
    const float* __restrict__ W_cf,
    const float* __restrict__ W_df,
    const float* __restrict__ W_fc,
    const float* __restrict__ b_cf,
    const float* __restrict__ b_df,
    float* __restrict__ out)
{
    extern __shared__ char smc[];
    const int tid = threadIdx.x;

    if (blockIdx.x == ATOM_CTAS) {
        for (int idx = tid; idx < 16384; idx += 512) {
            int n = idx >> 7, k = idx & 127;
            int o = n * BSTR + k;
            float vdf = (k < N_DIST) ? W_df[k * 128 + n] : 0.0f;
            g_Bdf_h[o] = __float2half_rn(vdf);
            g_Bfc_h[o] = __float2half_rn(W_fc[k * 128 + n]);
        }
        return;
    }

    float* bcf_s = (float*)(smc + ASM_IS);
    float* bdf_s = (float*)(smc + ASM_JS);
    const uint32_t sb  = smem_u32(smc);
    const uint32_t aHi = sb + ASM_AHI, aLo = sb + ASM_ALO;
    const uint32_t bHi = sb + ASM_BHI, bLo = sb + ASM_BLO;

    const int wid = tid >> 5, lane = tid & 31;
    const int rg = wid >> 2, cg = wid & 3;
    const int base  = blockIdx.x * TROWS;
    const int nrows = min(TROWS, N_ATOMS - base);

    if (tid < 128) { bcf_s[tid] = b_cf[tid]; bdf_s[tid] = b_df[tid]; }
    stage_splits_bf(smc, atom_features, base, nrows, tid);
    stage_w_direct(smc, W_cf, tid);
    __syncthreads();

    const int arow  = (lane & 7) + 8 * ((lane >> 3) & 1);
    const int acolb = 16 * (lane >> 4);
    const int brow  = (lane & 7) + 8 * (lane >> 4);
    const int bcolb = 16 * ((lane >> 3) & 1);
    const uint32_t aoff0 = (uint32_t)((rg * 64 + arow) * (BSTR * 2) + acolb);
    const uint32_t boff0 = (uint32_t)((cg * 32 + brow) * (BSTR * 2) + bcolb);

    float d[64];
#pragma unroll
    for (int i = 0; i < 64; i++) d[i] = 0.0f;
    do_gemm3<8>(aHi, aLo, bHi, bLo, aoff0, boff0, d);
    __syncthreads();

    // Epilogue 1: afh = d + b_cf -> g_afh (fp32); m = b_df*afh -> A splits
    {
        const int g = lane >> 2, tg = lane & 3;
#pragma unroll
        for (int mt = 0; mt < 4; mt++)
#pragma unroll
            for (int f2 = 0; f2 < 2; f2++) {
                const int row = rg * 64 + mt * 16 + 8 * f2 + g;
                const bool ok = row < nrows;
                char* ah = smc + ASM_AHI + row * (BSTR * 2);
                char* al = smc + ASM_ALO + row * (BSTR * 2);
                float* g2 = g_afh + (size_t)(base + row) * N_HID;
#pragma unroll
                for (int nt = 0; nt < 4; nt++) {
                    const int c = cg * 32 + nt * 8 + 2 * tg;
                    float a0 = d[(mt*4+nt)*4 + 2*f2]     + bcf_s[c];
                    float a1 = d[(mt*4+nt)*4 + 2*f2 + 1] + bcf_s[c + 1];
                    if (ok) *(float2*)(g2 + c) = make_float2(a0, a1);
                    float m0 = bdf_s[c] * a0, m1 = bdf_s[c + 1] * a1;
                    ushort_t h0, l0, h1, l1;
                    split_bf(m0, h0, l0); split_bf(m1, h1, l1);
                    *(unsigned*)(ah + c * 2) = (unsigned)h0 | ((unsigned)h1 << 16);
                    *(unsigned*)(al + c * 2) = (unsigned)l0 | ((unsigned)l1 << 16);
                }
            }
    }
    stage_w_direct(smc, W_fc, tid);
    __syncthreads();

#pragma unroll
    for (int i = 0; i < 64; i++) d[i] = 0.0f;
    do_gemm3<8>(aHi, aLo, bHi, bLo, aoff0, boff0, d);

    {
        const int g = lane >> 2, tg = lane & 3;
#pragma unroll
        for (int mt = 0; mt < 4; mt++)
#pragma unroll
            for (int f2 = 0; f2 < 2; f2++) {
                const int row = rg * 64 + mt * 16 + 8 * f2 + g;
                if (row < nrows) {
                    const float* afr = atom_features + (size_t)(base + row) * N_EMB;
                    float* orow = out + (size_t)(base + row) * N_EMB;
#pragma unroll
                    for (int nt = 0; nt < 4; nt++) {
                        const int c = cg * 32 + nt * 8 + 2 * tg;
                        float2 af = *(const float2*)(afr + c);
                        float2 ov;
                        ov.x = af.x - tanh_approx(d[(mt*4+nt)*4 + 2*f2]);
                        ov.y = af.y - tanh_approx(d[(mt*4+nt)*4 + 2*f2 + 1]);
                        *(float2*)(orow + c) = ov;
                    }
                }
            }
    }
}

// =====================================================================
// Pairs kernel (fp16 1-term, per-rg named barriers): 512 thr = 16 warps.
// After the initial full sync, each 4-warp row-group (rg) only syncs
// with itself: its A rows are private; W images are read-only.
// msg (tanh, fp16) is written in place into the rg's own A-quarter.
// =====================================================================
__global__ void __launch_bounds__(512, 1) pairs_kernel(
    const float* __restrict__ distance,
    const int*   __restrict__ dmi,
    const int*   __restrict__ dmj,
    const float* __restrict__ b_df,
    float* __restrict__ out)
{
    extern __shared__ char smc[];
    int*   i_s   = (int*)(smc + PSM_IS);
    int*   j_s   = (int*)(smc + PSM_JS);
    float* bdf_s = (float*)(smc + PSM_BDF);
    const uint32_t sb = smem_u32(smc);
    const uint32_t aB  = sb + PSM_A;
    const uint32_t wDF = sb + PSM_WDF;
    const uint32_t wFC = sb + PSM_WFC;

    const int tid = threadIdx.x;
    const int wid = tid >> 5, lane = tid & 31;
    const int rg = wid >> 2, cg = wid & 3;
    const int pbase = blockIdx.x * TROWS;

    {
        const int srow  = tid >> 1;
        const int shalf = tid & 1;
        if (!shalf) {
            i_s[srow]  = dmi[pbase + srow];
            j_s[srow]  = dmj[pbase + srow];
            if (srow < 128) bdf_s[srow] = b_df[srow];
        }
    }
    stage_half(smc, distance, pbase, tid);
    for (int q = tid; q < 2176; q += 512) {
        ((uint4*)(smc + PSM_WDF))[q] = ((const uint4*)g_Bdf_h)[q];
        ((uint4*)(smc + PSM_WFC))[q] = ((const uint4*)g_Bfc_h)[q];
    }
    __syncthreads();   // the only full-CTA barrier

    const int arow  = (lane & 7) + 8 * ((lane >> 3) & 1);
    const int acolb = 16 * (lane >> 4);
    const int brow  = (lane & 7) + 8 * (lane >> 4);
    const int bcolb = 16 * ((lane >> 3) & 1);
    const uint32_t aoff0 = (uint32_t)((rg * 64 + arow) * (BSTR * 2) + acolb);
    const uint32_t boff0 = (uint32_t)((cg * 32 + brow) * (BSTR * 2) + bcolb);

    float d[64];
#pragma unroll
    for (int i = 0; i < 64; i++) d[i] = 0.0f;

    // GEMM1: dh = dist @ W_df (K=112 incl. zero pad); reads own rg's A rows
    do_gemm1t<7>(aB, wDF, aoff0, boff0, d);
    RG_BAR(rg);   // rg's GEMM1 reads done before rg's epi1 overwrites

    // Epilogue 1: m = (dh + b_df) * afh[j] (fp32 gather); fp16 -> own A rows
    {
        const int g = lane >> 2, tg = lane & 3;
#pragma unroll
        for (int mt = 0; mt < 4; mt++)
#pragma unroll
            for (int f2 = 0; f2 < 2; f2++) {
                const int row = rg * 64 + mt * 16 + 8 * f2 + g;
                const int j = j_s[row];
                const float* ar = g_afh + (size_t)j * N_HID;
                char* ap = smc + PSM_A + row * (BSTR * 2);
#pragma unroll
                for (int nt = 0; nt < 4; nt++) {
                    const int c = cg * 32 + nt * 8 + 2 * tg;
                    float2 af = *(const float2*)(ar + c);
                    float v0 = (d[(mt*4+nt)*4 + 2*f2]     + bdf_s[c])     * af.x;
                    float v1 = (d[(mt*4+nt)*4 + 2*f2 + 1] + bdf_s[c + 1]) * af.y;
                    unsigned u = (unsigned)__half_as_ushort(__float2half_rn(v0))
                               | ((unsigned)__half_as_ushort(__float2half_rn(v1)) << 16);
                    *(unsigned*)(ap + c * 2) = u;
                }
            }
    }
    RG_BAR(rg);   // all of rg's m written before rg's GEMM2 reads

    // GEMM2: pre = m @ W_fc (K=128)
#pragma unroll
    for (int i = 0; i < 64; i++) d[i] = 0.0f;
    do_gemm1t<8>(aB, wFC, aoff0, boff0, d);
    RG_BAR(rg);   // rg's GEMM2 reads done before msg overwrite

    // Epilogue 2: msg = tanh(pre), fp16 in place (own A rows, stride 136)
    {
        const int g = lane >> 2, tg = lane & 3;
#pragma unroll
        for (int mt = 0; mt < 4; mt++)
#pragma unroll
            for (int f2 = 0; f2 < 2; f2++) {
                const int row = rg * 64 + mt * 16 + 8 * f2 + g;
                char* ap = smc + PSM_A + row * (BSTR * 2);
#pragma unroll
                for (int nt = 0; nt < 4; nt++) {
                    const int c = cg * 32 + nt * 8 + 2 * tg;
                    float t0 = tanh_approx(d[(mt*4+nt)*4 + 2*f2]);
                    float t1 = tanh_approx(d[(mt*4+nt)*4 + 2*f2 + 1]);
                    unsigned u = (unsigned)__half_as_ushort(__float2half_rn(t0))
                               | ((unsigned)__half_as_ushort(__float2half_rn(t1)) << 16);
                    *(unsigned*)(ap + c * 2) = u;
                }
            }
    }
    RG_BAR(rg);   // rg's msg complete

    // Segment sum over sorted i, per-rg: 128 threads x 64 own rows.
    {
        const int c  = tid & 127;            // col
        const int r0 = rg * 64;              // own rg's rows
        int   cur = i_s[r0];
        float sum = 0.0f;
        for (int rr = r0; rr < r0 + 64; rr++) {
            int ii = i_s[rr];
            if (ii != cur) {
                atomicAdd(out + (size_t)cur * N_EMB + c, sum);
                cur = ii; sum = 0.0f;
            }
            sum += __half2float(*(const __half*)(smc + PSM_A + rr * (BSTR * 2) + c * 2));
        }
        atomicAdd(out + (size_t)cur * N_EMB + c, sum);
    }
}

// =====================================================================
extern "C" void kernel_launch(void* const* d_in, const int* in_sizes, int n_in,
                              void* d_out, int out_size)
{
    const float* atom_features = (const float*)d_in[0];
    const float* distance      = (const float*)d_in[1];
    const int*   dmi           = (const int*)d_in[3];
    const int*   dmj           = (const int*)d_in[4];
    const float* W_cf          = (const float*)d_in[5];
    const float* W_df          = (const float*)d_in[6];
    const float* W_fc          = (const float*)d_in[7];
    const float* b_cf          = (const float*)d_in[8];
    const float* b_df          = (const float*)d_in[9];
    float*       out           = (float*)d_out;

    cudaFuncSetAttribute(atoms_kernel, cudaFuncAttributeMaxDynamicSharedMemorySize, ASM_TOTAL);
    cudaFuncSetAttribute(pairs_kernel, cudaFuncAttributeMaxDynamicSharedMemorySize, PSM_TOTAL);

    atoms_kernel<<<ATOM_CTAS + 1, 512, ASM_TOTAL>>>(
        atom_features, W_cf, W_df, W_fc, b_cf, b_df, out);
    pairs_kernel<<<N_PAIRS / TROWS, 512, PSM_TOTAL>>>(
        distance, dmi, dmj, b_df, out);
}

// round 16
// speedup vs baseline: 1.5896x; 1.0489x over previous
#include <cuda_runtime.h>
#include <cuda_bf16.h>
#include <cuda_fp16.h>
#include <cstdint>

#define N_ATOMS 50000
#define N_PAIRS 800000
#define N_EMB   128
#define N_DIST  100
#define N_HID   128
#define BSTR    136          // padded element row stride (272 B for 2B types)
#define TROWS   256          // rows per CTA tile (pairs & atoms)
#define ATOM_CTAS ((N_ATOMS + TROWS - 1) / TROWS)   // 196

typedef unsigned long long ull;
typedef unsigned short ushort_t;

// ---------------- device scratch ----------------
__device__ __align__(16) float g_afh[(size_t)N_ATOMS * N_HID];   // fp32, 25.6MB
__device__ __align__(16) __half g_Bdf_h[128 * BSTR];
__device__ __align__(16) __half g_Bfc_h[128 * BSTR];

// ---------------- helpers ----------------
static __device__ __forceinline__ float tanh_approx(float x) {
    float y;
    asm("tanh.approx.f32 %0, %1;" : "=f"(y) : "f"(x));
    return y;
}
static __device__ __forceinline__ void split_fp16(float x, ushort_t &h, ushort_t &l) {
    __half hh = __float2half_rn(x);
    float r = x - __half2float(hh);
    __half hl = __float2half_rn(r);
    h = __half_as_ushort(hh);
    l = __half_as_ushort(hl);
}
static __device__ __forceinline__ uint32_t smem_u32(const void* p) {
    uint32_t a;
    asm("{ .reg .u64 t; cvta.to.shared.u64 t, %1; cvt.u32.u64 %0, t; }"
        : "=r"(a) : "l"(p));
    return a;
}
static __device__ __forceinline__ void ldsm4(uint32_t* r, uint32_t addr) {
    asm volatile("ldmatrix.sync.aligned.m8n8.x4.shared.b16 {%0,%1,%2,%3}, [%4];"
                 : "=r"(r[0]), "=r"(r[1]), "=r"(r[2]), "=r"(r[3]) : "r"(addr));
}
static __device__ __forceinline__ void mma_f16(float* d, const uint32_t* a,
                                               const uint32_t* b) {
    asm volatile(
        "mma.sync.aligned.m16n8k16.row.col.f32.f16.f16.f32 "
        "{%0,%1,%2,%3}, {%4,%5,%6,%7}, {%8,%9}, {%0,%1,%2,%3};"
        : "+f"(d[0]), "+f"(d[1]), "+f"(d[2]), "+f"(d[3])
        : "r"(a[0]), "r"(a[1]), "r"(a[2]), "r"(a[3]), "r"(b[0]), "r"(b[1]));
}
#define RG_BAR(rg) asm volatile("bar.sync %0, %1;" :: "r"((rg) + 1), "r"(128) : "memory")

// ---------------- atoms kernel SMEM layout (fp16 2-term, both W) ---------
#define BSM_BCF   0                        // 128 float (512 B)
#define BSM_BDF   512                      // 128 float (512 B)
#define BSM_A     2048                     // 256 x 136 fp16 = 69632 B
#define BSM_WCFH  (BSM_A + 69632)          // 71680
#define BSM_WCFL  (BSM_WCFH + 34816)       // 106496
#define BSM_WFCH  (BSM_WCFL + 34816)       // 141312
#define BSM_WFCL  (BSM_WFCH + 34816)       // 176128
#define BSM_TOTAL (BSM_WFCL + 34816)       // 210944 B

// ---------------- pairs kernel SMEM layout (fp16 1-term, both W) ---------
#define PSM_IS    0                        // 256 int
#define PSM_JS    1024                     // 256 int
#define PSM_BDF   2048                     // 128 float
#define PSM_A     2560                     // 256 x 136 fp16 = 69632 B
#define PSM_WDF   (PSM_A + 69632)          // 72192  (34816 B)
#define PSM_WFC   (PSM_WDF + 34816)        // 107008 (34816 B)
#define PSM_TOTAL (PSM_WFC + 34816)        // 141824 B
// msg (fp16) is stored in-place in each rg's own A-quarter (stride 136)

// =====================================================================
// Warp GEMM, fp16 2-term (atoms): A single image, B hi/lo.
// 8 LDSM + 32 MMA per kstep per warp.
// =====================================================================
template<int KSTEPS>
static __device__ __forceinline__ void do_gemm2t(
    uint32_t aBase, uint32_t bHi, uint32_t bLo,
    uint32_t aoff0, uint32_t boff0, float* d)
{
#pragma unroll 1
    for (int ks = 0; ks < KSTEPS; ks++) {
        uint32_t Ah[4][4], Bh[4][2], Bl[4][2];
#pragma unroll
        for (int mt = 0; mt < 4; mt++) {
            uint32_t off = aoff0 + mt * (16 * BSTR * 2) + ks * 32;
            ldsm4(Ah[mt], aBase + off);
        }
#pragma unroll
        for (int np = 0; np < 2; np++) {
            uint32_t off = boff0 + np * (16 * BSTR * 2) + ks * 32;
            uint32_t th[4], tl[4];
            ldsm4(th, bHi + off);
            ldsm4(tl, bLo + off);
            Bh[2*np][0] = th[0]; Bh[2*np][1] = th[1];
            Bh[2*np+1][0] = th[2]; Bh[2*np+1][1] = th[3];
            Bl[2*np][0] = tl[0]; Bl[2*np][1] = tl[1];
            Bl[2*np+1][0] = tl[2]; Bl[2*np+1][1] = tl[3];
        }
#pragma unroll
        for (int mt = 0; mt < 4; mt++)
#pragma unroll
            for (int nt = 0; nt < 4; nt++) {
                float* dd = d + (mt * 4 + nt) * 4;
                mma_f16(dd, Ah[mt], Bh[nt]);
                mma_f16(dd, Ah[mt], Bl[nt]);
            }
    }
}

// =====================================================================
// Warp GEMM, fp16 1-term (pairs): 6 LDSM + 16 MMA per kstep per warp.
// =====================================================================
template<int KSTEPS>
static __device__ __forceinline__ void do_gemm1t(
    uint32_t aBase, uint32_t bBase,
    uint32_t aoff0, uint32_t boff0, float* d)
{
#pragma unroll 1
    for (int ks = 0; ks < KSTEPS; ks++) {
        uint32_t Ah[4][4], B[4][2];
#pragma unroll
        for (int mt = 0; mt < 4; mt++) {
            uint32_t off = aoff0 + mt * (16 * BSTR * 2) + ks * 32;
            ldsm4(Ah[mt], aBase + off);
        }
#pragma unroll
        for (int np = 0; np < 2; np++) {
            uint32_t off = boff0 + np * (16 * BSTR * 2) + ks * 32;
            uint32_t t[4];
            ldsm4(t, bBase + off);
            B[2*np][0] = t[0]; B[2*np][1] = t[1];
            B[2*np+1][0] = t[2]; B[2*np+1][1] = t[3];
        }
#pragma unroll
        for (int mt = 0; mt < 4; mt++)
#pragma unroll
            for (int nt = 0; nt < 4; nt++)
                mma_f16(d + (mt * 4 + nt) * 4, Ah[mt], B[nt]);
    }
}

// ======== staging helpers ========
// fp16 single-image staging of an fp32 matrix (2 threads per row),
// AOFF = smem byte offset of the A image, NC = source cols (100 or 128).
template<int AOFF, int NC>
static __device__ __forceinline__ void stage_half_t(
    char* smc, const float* __restrict__ src, int base, int nrows, int tid)
{
    const int srow  = tid >> 1;
    const int shalf = tid & 1;
    const int nq = NC / 4;
    const int q0 = shalf ? (nq + 1) / 2 : 0;
    const int q1 = shalf ? nq : (nq + 1) / 2;
    char* ap = smc + AOFF + srow * (BSTR * 2);
    if (srow < nrows) {
        const float4* dr = (const float4*)(src + (size_t)(base + srow) * NC);
#pragma unroll
        for (int q = q0; q < q1; q++) {
            float4 v = dr[q];
            unsigned u01 = (unsigned)__half_as_ushort(__float2half_rn(v.x))
                         | ((unsigned)__half_as_ushort(__float2half_rn(v.y)) << 16);
            unsigned u23 = (unsigned)__half_as_ushort(__float2half_rn(v.z))
                         | ((unsigned)__half_as_ushort(__float2half_rn(v.w)) << 16);
            *(unsigned*)(ap + 8 * q)     = u01;
            *(unsigned*)(ap + 8 * q + 4) = u23;
        }
    } else {
        for (int q = q0; q < q1; q++) *(ull*)(ap + 8 * q) = 0ULL;
    }
    if (NC < 128 && shalf) {
#pragma unroll
        for (int c = 100; c < 112; c += 2)   // zero pad for kstep 6
            *(unsigned*)(ap + c * 2) = 0u;
    }
}

// =====================================================================
// Atoms kernel (fp16 2-term, both W resident, per-rg barriers)
//   afh = A @ W_cf + b_cf -> g_afh (fp32)
//   out = A - tanh((b_df * afh) @ W_fc)
// blockIdx == ATOM_CTAS: prep CTA builds pairs' single fp16 W images.
// =====================================================================
__global__ void __launch_bounds__(512, 1) atoms_kernel(
    const float* __restrict__ atom_features,
    const float* __restrict__ W_cf,
    const float* __restrict__ W_df,
    const float* __restrict__ W_fc,
    const float* __restrict__ b_cf,
    const float* __restrict__ b_df,
    float* __restrict__ out)
{
    extern __shared__ char smc[];
    const int tid = threadIdx.x;

    if (blockIdx.x == ATOM_CTAS) {
        for (int idx = tid; idx < 16384; idx += 512) {
            int n = idx >> 7, k = idx & 127;
            int o = n * BSTR + k;
            float vdf = (k < N_DIST) ? W_df[k * 128 + n] : 0.0f;
            g_Bdf_h[o] = __float2half_rn(vdf);
            g_Bfc_h[o] = __float2half_rn(W_fc[k * 128 + n]);
        }
        return;
    }

    float* bcf_s = (float*)(smc + BSM_BCF);
    float* bdf_s = (float*)(smc + BSM_BDF);
    const uint32_t sb = smem_u32(smc);
    const uint32_t aB   = sb + BSM_A;
    const uint32_t wCFh = sb + BSM_WCFH, wCFl = sb + BSM_WCFL;
    const uint32_t wFCh = sb + BSM_WFCH, wFCl = sb + BSM_WFCL;

    const int wid = tid >> 5, lane = tid & 31;
    const int rg = wid >> 2, cg = wid & 3;
    const int base  = blockIdx.x * TROWS;
    const int nrows = min(TROWS, N_ATOMS - base);

    if (tid < 128) { bcf_s[tid] = b_cf[tid]; bdf_s[tid] = b_df[tid]; }
    stage_half_t<BSM_A, 128>(smc, atom_features, base, nrows, tid);
    {   // W_cf / W_fc hi/lo fp16 images, direct from fp32 (coalesced reads)
        __half* ch = (__half*)(smc + BSM_WCFH);
        __half* cl = (__half*)(smc + BSM_WCFL);
        __half* fh = (__half*)(smc + BSM_WFCH);
        __half* fl = (__half*)(smc + BSM_WFCL);
        for (int idx = tid; idx < 16384; idx += 512) {
            int k = idx >> 7, n = idx & 127;
            int o = n * BSTR + k;
            ushort_t h, l;
            split_fp16(W_cf[idx], h, l);
            ch[o] = __ushort_as_half(h); cl[o] = __ushort_as_half(l);
            split_fp16(W_fc[idx], h, l);
            fh[o] = __ushort_as_half(h); fl[o] = __ushort_as_half(l);
        }
    }
    __syncthreads();   // only full-CTA barrier

    const int arow  = (lane & 7) + 8 * ((lane >> 3) & 1);
    const int acolb = 16 * (lane >> 4);
    const int brow  = (lane & 7) + 8 * (lane >> 4);
    const int bcolb = 16 * ((lane >> 3) & 1);
    const uint32_t aoff0 = (uint32_t)((rg * 64 + arow) * (BSTR * 2) + acolb);
    const uint32_t boff0 = (uint32_t)((cg * 32 + brow) * (BSTR * 2) + bcolb);

    float d[64];
#pragma unroll
    for (int i = 0; i < 64; i++) d[i] = 0.0f;
    do_gemm2t<8>(aB, wCFh, wCFl, aoff0, boff0, d);
    RG_BAR(rg);   // rg's GEMM1 reads done before epi1 overwrites its A rows

    // Epilogue 1: afh = d + b_cf -> g_afh (fp32); m = b_df*afh -> own A rows
    {
        const int g = lane >> 2, tg = lane & 3;
#pragma unroll
        for (int mt = 0; mt < 4; mt++)
#pragma unroll
            for (int f2 = 0; f2 < 2; f2++) {
                const int row = rg * 64 + mt * 16 + 8 * f2 + g;
                const bool ok = row < nrows;
                char* ap = smc + BSM_A + row * (BSTR * 2);
                float* g2 = g_afh + (size_t)(base + row) * N_HID;
#pragma unroll
                for (int nt = 0; nt < 4; nt++) {
                    const int c = cg * 32 + nt * 8 + 2 * tg;
                    float a0 = d[(mt*4+nt)*4 + 2*f2]     + bcf_s[c];
                    float a1 = d[(mt*4+nt)*4 + 2*f2 + 1] + bcf_s[c + 1];
                    if (ok) *(float2*)(g2 + c) = make_float2(a0, a1);
                    float m0 = bdf_s[c] * a0, m1 = bdf_s[c + 1] * a1;
                    unsigned u = (unsigned)__half_as_ushort(__float2half_rn(m0))
                               | ((unsigned)__half_as_ushort(__float2half_rn(m1)) << 16);
                    *(unsigned*)(ap + c * 2) = u;
                }
            }
    }
    RG_BAR(rg);   // rg's m complete before its GEMM2 reads

    // GEMM2: pre = m @ W_fc (K=128)
#pragma unroll
    for (int i = 0; i < 64; i++) d[i] = 0.0f;
    do_gemm2t<8>(aB, wFCh, wFCl, aoff0, boff0, d);

    // Epilogue 2: out = atom_features - tanh(pre)   (gmem only; no barrier)
    {
        const int g = lane >> 2, tg = lane & 3;
#pragma unroll
        for (int mt = 0; mt < 4; mt++)
#pragma unroll
            for (int f2 = 0; f2 < 2; f2++) {
                const int row = rg * 64 + mt * 16 + 8 * f2 + g;
                if (row < nrows) {
                    const float* afr = atom_features + (size_t)(base + row) * N_EMB;
                    float* orow = out + (size_t)(base + row) * N_EMB;
#pragma unroll
                    for (int nt = 0; nt < 4; nt++) {
                        const int c = cg * 32 + nt * 8 + 2 * tg;
                        float2 af = *(const float2*)(afr + c);
                        float2 ov;
                        ov.x = af.x - tanh_approx(d[(mt*4+nt)*4 + 2*f2]);
                        ov.y = af.y - tanh_approx(d[(mt*4+nt)*4 + 2*f2 + 1]);
                        *(float2*)(orow + c) = ov;
                    }
                }
            }
    }
}

// =====================================================================
// Pairs kernel (fp16 1-term, per-rg named barriers): unchanged from R15.
// =====================================================================
__global__ void __launch_bounds__(512, 1) pairs_kernel(
    const float* __restrict__ distance,
    const int*   __restrict__ dmi,
    const int*   __restrict__ dmj,
    const float* __restrict__ b_df,
    float* __restrict__ out)
{
    extern __shared__ char smc[];
    int*   i_s   = (int*)(smc + PSM_IS);
    int*   j_s   = (int*)(smc + PSM_JS);
    float* bdf_s = (float*)(smc + PSM_BDF);
    const uint32_t sb = smem_u32(smc);
    const uint32_t aB  = sb + PSM_A;
    const uint32_t wDF = sb + PSM_WDF;
    const uint32_t wFC = sb + PSM_WFC;

    const int tid = threadIdx.x;
    const int wid = tid >> 5, lane = tid & 31;
    const int rg = wid >> 2, cg = wid & 3;
    const int pbase = blockIdx.x * TROWS;

    {
        const int srow  = tid >> 1;
        const int shalf = tid & 1;
        if (!shalf) {
            i_s[srow]  = dmi[pbase + srow];
            j_s[srow]  = dmj[pbase + srow];
            if (srow < 128) bdf_s[srow] = b_df[srow];
        }
    }
    stage_half_t<PSM_A, N_DIST>(smc, distance, pbase, TROWS, tid);
    for (int q = tid; q < 2176; q += 512) {
        ((uint4*)(smc + PSM_WDF))[q] = ((const uint4*)g_Bdf_h)[q];
        ((uint4*)(smc + PSM_WFC))[q] = ((const uint4*)g_Bfc_h)[q];
    }
    __syncthreads();   // the only full-CTA barrier

    const int arow  = (lane & 7) + 8 * ((lane >> 3) & 1);
    const int acolb = 16 * (lane >> 4);
    const int brow  = (lane & 7) + 8 * (lane >> 4);
    const int bcolb = 16 * ((lane >> 3) & 1);
    const uint32_t aoff0 = (uint32_t)((rg * 64 + arow) * (BSTR * 2) + acolb);
    const uint32_t boff0 = (uint32_t)((cg * 32 + brow) * (BSTR * 2) + bcolb);

    float d[64];
#pragma unroll
    for (int i = 0; i < 64; i++) d[i] = 0.0f;

    // GEMM1: dh = dist @ W_df (K=112 incl. zero pad)
    do_gemm1t<7>(aB, wDF, aoff0, boff0, d);
    RG_BAR(rg);

    // Epilogue 1: m = (dh + b_df) * afh[j] (fp32 gather); fp16 -> own A rows
    {
        const int g = lane >> 2, tg = lane & 3;
#pragma unroll
        for (int mt = 0; mt < 4; mt++)
#pragma unroll
            for (int f2 = 0; f2 < 2; f2++) {
                const int row = rg * 64 + mt * 16 + 8 * f2 + g;
                const int j = j_s[row];
                const float* ar = g_afh + (size_t)j * N_HID;
                char* ap = smc + PSM_A + row * (BSTR * 2);
#pragma unroll
                for (int nt = 0; nt < 4; nt++) {
                    const int c = cg * 32 + nt * 8 + 2 * tg;
                    float2 af = *(const float2*)(ar + c);
                    float v0 = (d[(mt*4+nt)*4 + 2*f2]     + bdf_s[c])     * af.x;
                    float v1 = (d[(mt*4+nt)*4 + 2*f2 + 1] + bdf_s[c + 1]) * af.y;
                    unsigned u = (unsigned)__half_as_ushort(__float2half_rn(v0))
                               | ((unsigned)__half_as_ushort(__float2half_rn(v1)) << 16);
                    *(unsigned*)(ap + c * 2) = u;
                }
            }
    }
    RG_BAR(rg);

    // GEMM2: pre = m @ W_fc (K=128)
#pragma unroll
    for (int i = 0; i < 64; i++) d[i] = 0.0f;
    do_gemm1t<8>(aB, wFC, aoff0, boff0, d);
    RG_BAR(rg);

    // Epilogue 2: msg = tanh(pre), fp16 in place (own A rows)
    {
        const int g = lane >> 2, tg = lane & 3;
#pragma unroll
        for (int mt = 0; mt < 4; mt++)
#pragma unroll
            for (int f2 = 0; f2 < 2; f2++) {
                const int row = rg * 64 + mt * 16 + 8 * f2 + g;
                char* ap = smc + PSM_A + row * (BSTR * 2);
#pragma unroll
                for (int nt = 0; nt < 4; nt++) {
                    const int c = cg * 32 + nt * 8 + 2 * tg;
                    float t0 = tanh_approx(d[(mt*4+nt)*4 + 2*f2]);
                    float t1 = tanh_approx(d[(mt*4+nt)*4 + 2*f2 + 1]);
                    unsigned u = (unsigned)__half_as_ushort(__float2half_rn(t0))
                               | ((unsigned)__half_as_ushort(__float2half_rn(t1)) << 16);
                    *(unsigned*)(ap + c * 2) = u;
                }
            }
    }
    RG_BAR(rg);

    // Segment sum over sorted i, per-rg: 128 threads x 64 own rows.
    {
        const int c  = tid & 127;
        const int r0 = rg * 64;
        int   cur = i_s[r0];
        float sum = 0.0f;
        for (int rr = r0; rr < r0 + 64; rr++) {
            int ii = i_s[rr];
            if (ii != cur) {
                atomicAdd(out + (size_t)cur * N_EMB + c, sum);
                cur = ii; sum = 0.0f;
            }
            sum += __half2float(*(const __half*)(smc + PSM_A + rr * (BSTR * 2) + c * 2));
        }
        atomicAdd(out + (size_t)cur * N_EMB + c, sum);
    }
}

// =====================================================================
extern "C" void kernel_launch(void* const* d_in, const int* in_sizes, int n_in,
                              void* d_out, int out_size)
{
    const float* atom_features = (const float*)d_in[0];
    const float* distance      = (const float*)d_in[1];
    const int*   dmi           = (const int*)d_in[3];
    const int*   dmj           = (const int*)d_in[4];
    const float* W_cf          = (const float*)d_in[5];
    const float* W_df          = (const float*)d_in[6];
    const float* W_fc          = (const float*)d_in[7];
    const float* b_cf          = (const float*)d_in[8];
    const float* b_df          = (const float*)d_in[9];
    float*       out           = (float*)d_out;

    cudaFuncSetAttribute(atoms_kernel, cudaFuncAttributeMaxDynamicSharedMemorySize, BSM_TOTAL);
    cudaFuncSetAttribute(pairs_kernel, cudaFuncAttributeMaxDynamicSharedMemorySize, PSM_TOTAL);

    atoms_kernel<<<ATOM_CTAS + 1, 512, BSM_TOTAL>>>(
        atom_features, W_cf, W_df, W_fc, b_cf, b_df, out);
    pairs_kernel<<<N_PAIRS / TROWS, 512, PSM_TOTAL>>>(
        distance, dmi, dmj, b_df, out);
}

// round 17
// speedup vs baseline: 1.6765x; 1.0547x over previous
#include <cuda_runtime.h>
#include <cuda_bf16.h>
#include <cuda_fp16.h>
#include <cstdint>

#define N_ATOMS 50000
#define N_PAIRS 800000
#define N_EMB   128
#define N_DIST  100
#define N_HID   128
#define BSTR    136          // padded element row stride (272 B for 2B types)
#define TROWS   256          // rows per CTA tile (pairs & atoms)
#define ATOM_CTAS ((N_ATOMS + TROWS - 1) / TROWS)   // 196

typedef unsigned long long ull;
typedef unsigned short ushort_t;

// ---------------- device scratch ----------------
__device__ __align__(16) __half g_afh_h[(size_t)N_ATOMS * N_HID];  // fp16, 12.8MB
__device__ __align__(16) __half g_Bdf_h[128 * BSTR];
__device__ __align__(16) __half g_Bfc_h[128 * BSTR];

// ---------------- helpers ----------------
static __device__ __forceinline__ float tanh_approx(float x) {
    float y;
    asm("tanh.approx.f32 %0, %1;" : "=f"(y) : "f"(x));
    return y;
}
static __device__ __forceinline__ uint32_t smem_u32(const void* p) {
    uint32_t a;
    asm("{ .reg .u64 t; cvta.to.shared.u64 t, %1; cvt.u32.u64 %0, t; }"
        : "=r"(a) : "l"(p));
    return a;
}
static __device__ __forceinline__ void ldsm4(uint32_t* r, uint32_t addr) {
    asm volatile("ldmatrix.sync.aligned.m8n8.x4.shared.b16 {%0,%1,%2,%3}, [%4];"
                 : "=r"(r[0]), "=r"(r[1]), "=r"(r[2]), "=r"(r[3]) : "r"(addr));
}
static __device__ __forceinline__ void mma_f16(float* d, const uint32_t* a,
                                               const uint32_t* b) {
    asm volatile(
        "mma.sync.aligned.m16n8k16.row.col.f32.f16.f16.f32 "
        "{%0,%1,%2,%3}, {%4,%5,%6,%7}, {%8,%9}, {%0,%1,%2,%3};"
        : "+f"(d[0]), "+f"(d[1]), "+f"(d[2]), "+f"(d[3])
        : "r"(a[0]), "r"(a[1]), "r"(a[2]), "r"(a[3]), "r"(b[0]), "r"(b[1]));
}
static __device__ __forceinline__ unsigned pack_half2(float a, float b) {
    return (unsigned)__half_as_ushort(__float2half_rn(a))
         | ((unsigned)__half_as_ushort(__float2half_rn(b)) << 16);
}
#define RG_BAR(rg) asm volatile("bar.sync %0, %1;" :: "r"((rg) + 1), "r"(128) : "memory")

// ---------------- atoms kernel SMEM layout (fp16 1-term, both W) ---------
#define BSM_BCF   0                        // 128 float (512 B)
#define BSM_BDF   512                      // 128 float (512 B)
#define BSM_A     2048                     // 256 x 136 fp16 = 69632 B
#define BSM_WCF   (BSM_A + 69632)          // 71680  (34816 B)
#define BSM_WFC   (BSM_WCF + 34816)        // 106496 (34816 B)
#define BSM_TOTAL (BSM_WFC + 34816)        // 141312 B

// ---------------- pairs kernel SMEM layout (fp16 1-term, both W) ---------
#define PSM_IS    0                        // 256 int
#define PSM_JS    1024                     // 256 int
#define PSM_BDF   2048                     // 128 float
#define PSM_A     2560                     // 256 x 136 fp16 = 69632 B
#define PSM_WDF   (PSM_A + 69632)          // 72192  (34816 B)
#define PSM_WFC   (PSM_WDF + 34816)        // 107008 (34816 B)
#define PSM_TOTAL (PSM_WFC + 34816)        // 141824 B
// msg (fp16) stored in-place in each rg's own A-quarter (stride 136)

// =====================================================================
// Warp GEMM, fp16 1-term: 6 LDSM + 16 MMA per kstep per warp.
// D[256,128] over 16 warps (4 rg x 4 cg), warp tile 64x32.
// =====================================================================
template<int KSTEPS>
static __device__ __forceinline__ void do_gemm1t(
    uint32_t aBase, uint32_t bBase,
    uint32_t aoff0, uint32_t boff0, float* d)
{
#pragma unroll 1
    for (int ks = 0; ks < KSTEPS; ks++) {
        uint32_t Ah[4][4], B[4][2];
#pragma unroll
        for (int mt = 0; mt < 4; mt++) {
            uint32_t off = aoff0 + mt * (16 * BSTR * 2) + ks * 32;
            ldsm4(Ah[mt], aBase + off);
        }
#pragma unroll
        for (int np = 0; np < 2; np++) {
            uint32_t off = boff0 + np * (16 * BSTR * 2) + ks * 32;
            uint32_t t[4];
            ldsm4(t, bBase + off);
            B[2*np][0] = t[0]; B[2*np][1] = t[1];
            B[2*np+1][0] = t[2]; B[2*np+1][1] = t[3];
        }
#pragma unroll
        for (int mt = 0; mt < 4; mt++)
#pragma unroll
            for (int nt = 0; nt < 4; nt++)
                mma_f16(d + (mt * 4 + nt) * 4, Ah[mt], B[nt]);
    }
}

// ======== staging helpers ========
// fp16 single-image staging of an fp32 matrix (2 threads per row),
// AOFF = smem byte offset of the A image, NC = source cols (100 or 128).
template<int AOFF, int NC>
static __device__ __forceinline__ void stage_half_t(
    char* smc, const float* __restrict__ src, int base, int nrows, int tid)
{
    const int srow  = tid >> 1;
    const int shalf = tid & 1;
    const int nq = NC / 4;
    const int q0 = shalf ? (nq + 1) / 2 : 0;
    const int q1 = shalf ? nq : (nq + 1) / 2;
    char* ap = smc + AOFF + srow * (BSTR * 2);
    if (srow < nrows) {
        const float4* dr = (const float4*)(src + (size_t)(base + srow) * NC);
#pragma unroll
        for (int q = q0; q < q1; q++) {
            float4 v = dr[q];
            *(unsigned*)(ap + 8 * q)     = pack_half2(v.x, v.y);
            *(unsigned*)(ap + 8 * q + 4) = pack_half2(v.z, v.w);
        }
    } else {
        for (int q = q0; q < q1; q++) *(ull*)(ap + 8 * q) = 0ULL;
    }
    if (NC < 128 && shalf) {
#pragma unroll
        for (int c = 100; c < 112; c += 2)   // zero pad for kstep 6
            *(unsigned*)(ap + c * 2) = 0u;
    }
}

// =====================================================================
// Atoms kernel (fp16 1-term, both W resident, per-rg barriers)
//   afh = A @ W_cf + b_cf -> g_afh_h (fp16)
//   out = A - tanh((b_df * afh) @ W_fc)
// blockIdx == ATOM_CTAS: prep CTA builds pairs' fp16 W images.
// =====================================================================
__global__ void __launch_bounds__(512, 1) atoms_kernel(
    const float* __restrict__ atom_features,
    const float* __restrict__ W_cf,
    const float* __restrict__ W_df,
    const float* __restrict__ W_fc,
    const float* __restrict__ b_cf,
    const float* __restrict__ b_df,
    float* __restrict__ out)
{
    extern __shared__ char smc[];
    const int tid = threadIdx.x;

    if (blockIdx.x == ATOM_CTAS) {
        for (int idx = tid; idx < 16384; idx += 512) {
            int n = idx >> 7, k = idx & 127;
            int o = n * BSTR + k;
            float vdf = (k < N_DIST) ? W_df[k * 128 + n] : 0.0f;
            g_Bdf_h[o] = __float2half_rn(vdf);
            g_Bfc_h[o] = __float2half_rn(W_fc[k * 128 + n]);
        }
        return;
    }

    float* bcf_s = (float*)(smc + BSM_BCF);
    float* bdf_s = (float*)(smc + BSM_BDF);
    const uint32_t sb = smem_u32(smc);
    const uint32_t aB  = sb + BSM_A;
    const uint32_t wCF = sb + BSM_WCF;
    const uint32_t wFC = sb + BSM_WFC;

    const int wid = tid >> 5, lane = tid & 31;
    const int rg = wid >> 2, cg = wid & 3;
    const int base  = blockIdx.x * TROWS;
    const int nrows = min(TROWS, N_ATOMS - base);

    if (tid < 128) { bcf_s[tid] = b_cf[tid]; bdf_s[tid] = b_df[tid]; }
    stage_half_t<BSM_A, 128>(smc, atom_features, base, nrows, tid);
    {   // W_cf / W_fc single fp16 images, direct from fp32 (coalesced reads)
        __half* ch = (__half*)(smc + BSM_WCF);
        __half* fh = (__half*)(smc + BSM_WFC);
        for (int idx = tid; idx < 16384; idx += 512) {
            int k = idx >> 7, n = idx & 127;
            int o = n * BSTR + k;
            ch[o] = __float2half_rn(W_cf[idx]);
            fh[o] = __float2half_rn(W_fc[idx]);
        }
    }
    __syncthreads();   // only full-CTA barrier

    const int arow  = (lane & 7) + 8 * ((lane >> 3) & 1);
    const int acolb = 16 * (lane >> 4);
    const int brow  = (lane & 7) + 8 * (lane >> 4);
    const int bcolb = 16 * ((lane >> 3) & 1);
    const uint32_t aoff0 = (uint32_t)((rg * 64 + arow) * (BSTR * 2) + acolb);
    const uint32_t boff0 = (uint32_t)((cg * 32 + brow) * (BSTR * 2) + bcolb);

    float d[64];
#pragma unroll
    for (int i = 0; i < 64; i++) d[i] = 0.0f;
    do_gemm1t<8>(aB, wCF, aoff0, boff0, d);
    RG_BAR(rg);   // rg's GEMM1 reads done before epi1 overwrites its A rows

    // Epilogue 1: afh = d + b_cf -> g_afh_h (fp16); m = b_df*afh -> own A rows
    {
        const int g = lane >> 2, tg = lane & 3;
#pragma unroll
        for (int mt = 0; mt < 4; mt++)
#pragma unroll
            for (int f2 = 0; f2 < 2; f2++) {
                const int row = rg * 64 + mt * 16 + 8 * f2 + g;
                const bool ok = row < nrows;
                char* ap = smc + BSM_A + row * (BSTR * 2);
                __half* g2 = g_afh_h + (size_t)(base + row) * N_HID;
#pragma unroll
                for (int nt = 0; nt < 4; nt++) {
                    const int c = cg * 32 + nt * 8 + 2 * tg;
                    float a0 = d[(mt*4+nt)*4 + 2*f2]     + bcf_s[c];
                    float a1 = d[(mt*4+nt)*4 + 2*f2 + 1] + bcf_s[c + 1];
                    if (ok) *(unsigned*)(g2 + c) = pack_half2(a0, a1);
                    float m0 = bdf_s[c] * a0, m1 = bdf_s[c + 1] * a1;
                    *(unsigned*)(ap + c * 2) = pack_half2(m0, m1);
                }
            }
    }
    RG_BAR(rg);   // rg's m complete before its GEMM2 reads

    // GEMM2: pre = m @ W_fc (K=128)
#pragma unroll
    for (int i = 0; i < 64; i++) d[i] = 0.0f;
    do_gemm1t<8>(aB, wFC, aoff0, boff0, d);

    // Epilogue 2: out = atom_features - tanh(pre)   (gmem only; no barrier)
    {
        const int g = lane >> 2, tg = lane & 3;
#pragma unroll
        for (int mt = 0; mt < 4; mt++)
#pragma unroll
            for (int f2 = 0; f2 < 2; f2++) {
                const int row = rg * 64 + mt * 16 + 8 * f2 + g;
                if (row < nrows) {
                    const float* afr = atom_features + (size_t)(base + row) * N_EMB;
                    float* orow = out + (size_t)(base + row) * N_EMB;
#pragma unroll
                    for (int nt = 0; nt < 4; nt++) {
                        const int c = cg * 32 + nt * 8 + 2 * tg;
                        float2 af = *(const float2*)(afr + c);
                        float2 ov;
                        ov.x = af.x - tanh_approx(d[(mt*4+nt)*4 + 2*f2]);
                        ov.y = af.y - tanh_approx(d[(mt*4+nt)*4 + 2*f2 + 1]);
                        *(float2*)(orow + c) = ov;
                    }
                }
            }
    }
}

// =====================================================================
// Pairs kernel (fp16 1-term, per-rg named barriers; fp16 afh gather).
// =====================================================================
__global__ void __launch_bounds__(512, 1) pairs_kernel(
    const float* __restrict__ distance,
    const int*   __restrict__ dmi,
    const int*   __restrict__ dmj,
    const float* __restrict__ b_df,
    float* __restrict__ out)
{
    extern __shared__ char smc[];
    int*   i_s   = (int*)(smc + PSM_IS);
    int*   j_s   = (int*)(smc + PSM_JS);
    float* bdf_s = (float*)(smc + PSM_BDF);
    const uint32_t sb = smem_u32(smc);
    const uint32_t aB  = sb + PSM_A;
    const uint32_t wDF = sb + PSM_WDF;
    const uint32_t wFC = sb + PSM_WFC;

    const int tid = threadIdx.x;
    const int wid = tid >> 5, lane = tid & 31;
    const int rg = wid >> 2, cg = wid & 3;
    const int pbase = blockIdx.x * TROWS;

    {
        const int srow  = tid >> 1;
        const int shalf = tid & 1;
        if (!shalf) {
            i_s[srow]  = dmi[pbase + srow];
            j_s[srow]  = dmj[pbase + srow];
            if (srow < 128) bdf_s[srow] = b_df[srow];
        }
    }
    stage_half_t<PSM_A, N_DIST>(smc, distance, pbase, TROWS, tid);
    for (int q = tid; q < 2176; q += 512) {
        ((uint4*)(smc + PSM_WDF))[q] = ((const uint4*)g_Bdf_h)[q];
        ((uint4*)(smc + PSM_WFC))[q] = ((const uint4*)g_Bfc_h)[q];
    }
    __syncthreads();   // the only full-CTA barrier

    const int arow  = (lane & 7) + 8 * ((lane >> 3) & 1);
    const int acolb = 16 * (lane >> 4);
    const int brow  = (lane & 7) + 8 * (lane >> 4);
    const int bcolb = 16 * ((lane >> 3) & 1);
    const uint32_t aoff0 = (uint32_t)((rg * 64 + arow) * (BSTR * 2) + acolb);
    const uint32_t boff0 = (uint32_t)((cg * 32 + brow) * (BSTR * 2) + bcolb);

    float d[64];
#pragma unroll
    for (int i = 0; i < 64; i++) d[i] = 0.0f;

    // GEMM1: dh = dist @ W_df (K=112 incl. zero pad)
    do_gemm1t<7>(aB, wDF, aoff0, boff0, d);
    RG_BAR(rg);

    // Epilogue 1: m = (dh + b_df) * afh[j] (fp16 gather); fp16 -> own A rows
    {
        const int g = lane >> 2, tg = lane & 3;
#pragma unroll
        for (int mt = 0; mt < 4; mt++)
#pragma unroll
            for (int f2 = 0; f2 < 2; f2++) {
                const int row = rg * 64 + mt * 16 + 8 * f2 + g;
                const int j = j_s[row];
                const __half* ar = g_afh_h + (size_t)j * N_HID;
                char* ap = smc + PSM_A + row * (BSTR * 2);
#pragma unroll
                for (int nt = 0; nt < 4; nt++) {
                    const int c = cg * 32 + nt * 8 + 2 * tg;
                    __half2 ah2 = *(const __half2*)(ar + c);
                    float2 af = __half22float2(ah2);
                    float v0 = (d[(mt*4+nt)*4 + 2*f2]     + bdf_s[c])     * af.x;
                    float v1 = (d[(mt*4+nt)*4 + 2*f2 + 1] + bdf_s[c + 1]) * af.y;
                    *(unsigned*)(ap + c * 2) = pack_half2(v0, v1);
                }
            }
    }
    RG_BAR(rg);

    // GEMM2: pre = m @ W_fc (K=128)
#pragma unroll
    for (int i = 0; i < 64; i++) d[i] = 0.0f;
    do_gemm1t<8>(aB, wFC, aoff0, boff0, d);
    RG_BAR(rg);

    // Epilogue 2: msg = tanh(pre), fp16 in place (own A rows)
    {
        const int g = lane >> 2, tg = lane & 3;
#pragma unroll
        for (int mt = 0; mt < 4; mt++)
#pragma unroll
            for (int f2 = 0; f2 < 2; f2++) {
                const int row = rg * 64 + mt * 16 + 8 * f2 + g;
                char* ap = smc + PSM_A + row * (BSTR * 2);
#pragma unroll
                for (int nt = 0; nt < 4; nt++) {
                    const int c = cg * 32 + nt * 8 + 2 * tg;
                    float t0 = tanh_approx(d[(mt*4+nt)*4 + 2*f2]);
                    float t1 = tanh_approx(d[(mt*4+nt)*4 + 2*f2 + 1]);
                    *(unsigned*)(ap + c * 2) = pack_half2(t0, t1);
                }
            }
    }
    RG_BAR(rg);

    // Segment sum over sorted i, per-rg: 128 threads x 64 own rows.
    {
        const int c  = tid & 127;
        const int r0 = rg * 64;
        int   cur = i_s[r0];
        float sum = 0.0f;
        for (int rr = r0; rr < r0 + 64; rr++) {
            int ii = i_s[rr];
            if (ii != cur) {
                atomicAdd(out + (size_t)cur * N_EMB + c, sum);
                cur = ii; sum = 0.0f;
            }
            sum += __half2float(*(const __half*)(smc + PSM_A + rr * (BSTR * 2) + c * 2));
        }
        atomicAdd(out + (size_t)cur * N_EMB + c, sum);
    }
}

// =====================================================================
extern "C" void kernel_launch(void* const* d_in, const int* in_sizes, int n_in,
                              void* d_out, int out_size)
{
    const float* atom_features = (const float*)d_in[0];
    const float* distance      = (const float*)d_in[1];
    const int*   dmi           = (const int*)d_in[3];
    const int*   dmj           = (const int*)d_in[4];
    const float* W_cf          = (const float*)d_in[5];
    const float* W_df          = (const float*)d_in[6];
    const float* W_fc          = (const float*)d_in[7];
    const float* b_cf          = (const float*)d_in[8];
    const float* b_df          = (const float*)d_in[9];
    float*       out           = (float*)d_out;

    cudaFuncSetAttribute(atoms_kernel, cudaFuncAttributeMaxDynamicSharedMemorySize, BSM_TOTAL);
    cudaFuncSetAttribute(pairs_kernel, cudaFuncAttributeMaxDynamicSharedMemorySize, PSM_TOTAL);

    atoms_kernel<<<ATOM_CTAS + 1, 512, BSM_TOTAL>>>(
        atom_features, W_cf, W_df, W_fc, b_cf, b_df, out);
    pairs_kernel<<<N_PAIRS / TROWS, 512, PSM_TOTAL>>>(
        distance, dmi, dmj, b_df, out);
}